// round 13
// baseline (speedup 1.0000x reference)
#include <cuda_runtime.h>
#include <cuda_bf16.h>
#include <cstdint>

typedef uint32_t u32;
typedef unsigned short u16;

#define NTHR   512
#define TILE_E 32          // per group (4 groups)
#define K1     214

#define STA  272           // A/h1 row stride bytes (136 bf16)
#define STW1 464           // W1 row stride (232 bf16)
#define STW2 272

#define A_PART   8704      // 32 rows * STA
#define OFF_B1S  0
#define OFF_B2S  512
#define OFF_W3S  640
#define OFF_B3S  896
#define OFF_A0   1024      // group g A: hi at OFF_A0+g*2*A_PART, lo at +A_PART
#define OFF_W1H  (OFF_A0 + 8 * A_PART)          // 70656
#define OFF_W1L  (OFF_W1H + 128 * STW1)         // 130048
#define OFF_W2H  (OFF_W1L + 128 * STW1)         // 189440
#define OFF_W2L  (OFF_W2H + 32 * STW2)          // 198144
#define OFF_H2   (OFF_W2L + 32 * STW2)          // 206848; per group +4352
#define SMEM_SZ  (OFF_H2 + 4 * 32 * 34 * 4)     // 224256 B

__device__ __forceinline__ u32 s2u(const void* p) {
    u32 a;
    asm("{ .reg .u64 t; cvta.to.shared.u64 t, %1; cvt.u32.u64 %0, t; }" : "=r"(a) : "l"(p));
    return a;
}
__device__ __forceinline__ void ldm4(u32 addr, u32* r) {
    asm volatile("ldmatrix.sync.aligned.m8n8.x4.shared.b16 {%0,%1,%2,%3}, [%4];"
                 : "=r"(r[0]), "=r"(r[1]), "=r"(r[2]), "=r"(r[3]) : "r"(addr));
}
__device__ __forceinline__ void ldm2(u32 addr, u32* r) {
    asm volatile("ldmatrix.sync.aligned.m8n8.x2.shared.b16 {%0,%1}, [%2];"
                 : "=r"(r[0]), "=r"(r[1]) : "r"(addr));
}
__device__ __forceinline__ void mma_bf16(float* c, const u32* a, u32 b0, u32 b1) {
    asm volatile("mma.sync.aligned.m16n8k16.row.col.f32.bf16.bf16.f32 "
                 "{%0,%1,%2,%3}, {%4,%5,%6,%7}, {%8,%9}, {%0,%1,%2,%3};"
                 : "+f"(c[0]), "+f"(c[1]), "+f"(c[2]), "+f"(c[3])
                 : "r"(a[0]), "r"(a[1]), "r"(a[2]), "r"(a[3]), "r"(b0), "r"(b1));
}
__device__ __forceinline__ u32 cvt2(float a, float b) {
    u32 r;
    asm("cvt.rn.bf16x2.f32 %0, %2, %1;" : "=r"(r) : "f"(a), "f"(b));
    return r;
}
__device__ __forceinline__ void splitp(float a, float b, u32& hp, u32& lp) {
    u32 ua = __float_as_uint(a), ub = __float_as_uint(b);
    hp = __byte_perm(ua, ub, 0x7632);
    float ra = a - __uint_as_float(ua & 0xFFFF0000u);
    float rb = b - __uint_as_float(ub & 0xFFFF0000u);
    lp = cvt2(ra, rb);
}
// split 8 floats and store 16B hi at base+wb, 16B lo at base+A_PART+wb
__device__ __forceinline__ void sts_split8(char* smem, u32 base, u32 wb, const float* v) {
    uint4 hv, lv;
    splitp(v[0], v[1], hv.x, lv.x);
    splitp(v[2], v[3], hv.y, lv.y);
    splitp(v[4], v[5], hv.z, lv.z);
    splitp(v[6], v[7], hv.w, lv.w);
    *(uint4*)(smem + base + wb) = hv;
    *(uint4*)(smem + base + A_PART + wb) = lv;
}

// layer-1 chunk, term-outer ordering; warp tile 32 rows x 32 cols
template <int NKS>
__device__ __forceinline__ void l1_chunk(float (&acc)[2][4][4],
                                         u32 aBH, u32 aBL,
                                         u32 b1H, u32 b1L, u32 bk)
{
    #pragma unroll
    for (int ks = 0; ks < NKS; ++ks) {
        u32 ah[2][4], al[2][4], bh[2][4], bl[2][4];
        #pragma unroll
        for (int mb = 0; mb < 2; ++mb) {
            ldm4(aBH + mb * (16 * STA) + ks * 32, ah[mb]);
            ldm4(aBL + mb * (16 * STA) + ks * 32, al[mb]);
        }
        #pragma unroll
        for (int np = 0; np < 2; ++np) {
            ldm4(b1H + np * (16 * STW1) + bk + ks * 32, bh[np]);
            ldm4(b1L + np * (16 * STW1) + bk + ks * 32, bl[np]);
        }
        #pragma unroll
        for (int np = 0; np < 2; ++np)
            #pragma unroll
            for (int mb = 0; mb < 2; ++mb) {
                mma_bf16(acc[mb][2 * np],     ah[mb], bh[np][0], bh[np][1]);
                mma_bf16(acc[mb][2 * np + 1], ah[mb], bh[np][2], bh[np][3]);
            }
        #pragma unroll
        for (int np = 0; np < 2; ++np)
            #pragma unroll
            for (int mb = 0; mb < 2; ++mb) {
                mma_bf16(acc[mb][2 * np],     al[mb], bh[np][0], bh[np][1]);
                mma_bf16(acc[mb][2 * np + 1], al[mb], bh[np][2], bh[np][3]);
            }
        #pragma unroll
        for (int np = 0; np < 2; ++np)
            #pragma unroll
            for (int mb = 0; mb < 2; ++mb) {
                mma_bf16(acc[mb][2 * np],     ah[mb], bl[np][0], bl[np][1]);
                mma_bf16(acc[mb][2 * np + 1], ah[mb], bl[np][2], bl[np][3]);
            }
    }
}

extern "C" __global__ void __launch_bounds__(NTHR, 1)
edge_mlp_hmma(const float* __restrict__ x, const float* __restrict__ efeat,
              const float* __restrict__ nodef, const float* __restrict__ edgef,
              const int* __restrict__ src, const int* __restrict__ dst,
              const float* __restrict__ W1, const float* __restrict__ b1,
              const float* __restrict__ W2, const float* __restrict__ b2,
              const float* __restrict__ W3, const float* __restrict__ b3,
              float* __restrict__ out, int E, int ntiles)
{
    extern __shared__ char smem[];
    const u32 sb   = s2u(smem);
    const int tid  = threadIdx.x;
    const int g    = tid >> 7;          // pipeline group 0..3
    const int gt   = tid & 127;         // thread within group
    const int wg   = gt >> 5;           // warp within group (0..3)
    const int lane = tid & 31;
    const int barid = g + 1;            // named barrier id for this group

    const u32 aBase = OFF_A0 + (u32)g * (2 * A_PART);   // hi base; lo = +A_PART

    const int gm = gt >> 2, gq = gt & 3;  // gather: 4 threads per edge (32 edges)

    // ---------- initial prefetch: this group's tile-0 chunk0 ----------
    int sN, dN;
    bool ve;
    float4 rc0[8];
    {
        const int eg = (blockIdx.x * 4 + g) * TILE_E + gm;
        ve = eg < E;
        sN = ve ? src[eg] : 0;
        dN = ve ? dst[eg] : 0;
        const float4* p = (const float4*)((gq < 2) ? (x + (size_t)sN * 64 + gq * 32)
                                                   : (x + (size_t)dN * 64 + (gq - 2) * 32));
        #pragma unroll
        for (int i = 0; i < 8; ++i) rc0[i] = p[i];
    }

    // ---------- one-time weight staging (whole block) ----------
    for (int i = tid; i < 128 * 232; i += NTHR) {
        const int j = i / 232, k = i - j * 232;
        const float v = (k < K1) ? W1[j * K1 + k] : 0.f;
        const u32 uv = __float_as_uint(v);
        *(u16*)(smem + OFF_W1H + j * STW1 + k * 2) = (u16)(uv >> 16);
        const float r = v - __uint_as_float(uv & 0xFFFF0000u);
        const __nv_bfloat16 rb = __float2bfloat16(r);
        *(u16*)(smem + OFF_W1L + j * STW1 + k * 2) = *(const u16*)&rb;
    }
    for (int i = tid; i < 32 * 136; i += NTHR) {
        const int j = i / 136, k = i - j * 136;
        const float v = (k < 128) ? W2[j * 128 + k] : 0.f;
        const u32 uv = __float_as_uint(v);
        *(u16*)(smem + OFF_W2H + j * STW2 + k * 2) = (u16)(uv >> 16);
        const float r = v - __uint_as_float(uv & 0xFFFF0000u);
        const __nv_bfloat16 rb = __float2bfloat16(r);
        *(u16*)(smem + OFF_W2L + j * STW2 + k * 2) = *(const u16*)&rb;
    }
    if (tid < 128) ((float*)(smem + OFF_B1S))[tid] = b1[tid];
    if (tid < 32)  ((float*)(smem + OFF_B2S))[tid] = b2[tid];
    if (tid < 64)  ((float*)(smem + OFF_W3S))[tid] = W3[tid];
    if (tid < 2)   ((float*)(smem + OFF_B3S))[tid] = b3[tid];

    // ---------- per-lane fragment addresses (group-local; warp = n-quarter) ----------
    const int nq = wg;            // n-quarter: layer1 cols nq*32 .. +31; layer2 cols nq*8
    const int aRow = ((lane >> 3) & 1) * 8 + (lane & 7);
    const u32 aOff = (u32)aRow * STA + (u32)(lane >> 4) * 16;
    const u32 aBH  = sb + aBase + aOff;
    const u32 aBL  = aBH + A_PART;
    const int bSel = lane >> 4, bKh = (lane >> 3) & 1, bRow = lane & 7;
    const u32 b1off = (u32)(nq * 32 + bSel * 8 + bRow) * STW1 + (u32)bKh * 16;
    const u32 b1H  = sb + OFF_W1H + b1off;
    const u32 b1L  = sb + OFF_W1L + b1off;
    const u32 b2off = (u32)(nq * 8 + (lane & 7)) * STW2 + (u32)((lane >> 3) & 1) * 16;
    const u32 b2H  = sb + OFF_W2H + b2off;
    const u32 b2L  = sb + OFF_W2L + b2off;

    const float* b1s = (const float*)(smem + OFF_B1S);
    const float* b2s = (const float*)(smem + OFF_B2S);
    const float* W3s = (const float*)(smem + OFF_W3S);
    const float* b3s = (const float*)(smem + OFF_B3S);
    float* h2s = (float*)(smem + OFF_H2 + g * 4352);   // [32][34] f32

    __syncthreads();   // weights staged (block-wide, once)

    #define GBAR() asm volatile("bar.sync %0, %1;" :: "r"(barid), "n"(128) : "memory")

    for (int tile = blockIdx.x * 4 + g; tile < ntiles; tile += gridDim.x * 4) {
        const int ebase = tile * TILE_E;
        const int  eg   = ebase + gm;
        const size_t egc = ve ? (size_t)eg : 0;

        // ---------- STS chunk0 from prefetched registers ----------
        {
            const float* v = (const float*)rc0;
            const u32 wb = (u32)gm * STA + (u32)gq * 64;
            #pragma unroll
            for (int t8 = 0; t8 < 4; ++t8)
                sts_split8(smem, aBase, wb + t8 * 16, v + 8 * t8);
        }

        // ---------- prefetch chunk1 -> registers ----------
        float4 rc1[8];
        if (gq < 2) {
            const float4* p = (const float4*)(efeat + egc * 64 + gq * 32);
            #pragma unroll
            for (int i = 0; i < 8; ++i) rc1[i] = p[i];
        } else if (gq == 2) {
            // nf_s(10) + nf_d(0..5): chunk1 cols 64..79
            float* v = (float*)rc1;
            #pragma unroll
            for (int j = 0; j < 10; ++j) v[j] = nodef[(size_t)sN * 10 + j];
            #pragma unroll
            for (int j = 0; j < 6; ++j)  v[10 + j] = nodef[(size_t)dN * 10 + j];
        } else {
            // nf_d(6..9) + ef(2) + pad: chunk1 cols 80..95
            float* v = (float*)rc1;
            #pragma unroll
            for (int j = 0; j < 4; ++j) v[j] = nodef[(size_t)dN * 10 + 6 + j];
            v[4] = edgef[egc * 2];
            v[5] = edgef[egc * 2 + 1];
            #pragma unroll
            for (int j = 6; j < 16; ++j) v[j] = 0.f;
        }
        GBAR();

        float acc[2][4][4];
        #pragma unroll
        for (int i = 0; i < 2; ++i)
            #pragma unroll
            for (int j = 0; j < 4; ++j)
                #pragma unroll
                for (int p = 0; p < 4; ++p) acc[i][j][p] = 0.f;

        l1_chunk<8>(acc, aBH, aBL, b1H, b1L, 0);
        GBAR();

        // ---------- STS chunk1 (A cols 0..95 reused for k=128..223) ----------
        if (gq < 2) {
            const float* v = (const float*)rc1;
            const u32 wb = (u32)gm * STA + (u32)gq * 64;
            #pragma unroll
            for (int t8 = 0; t8 < 4; ++t8)
                sts_split8(smem, aBase, wb + t8 * 16, v + 8 * t8);
        } else {
            const float* v = (const float*)rc1;
            const u32 wb = (u32)gm * STA + 128 + (u32)(gq - 2) * 32;
            #pragma unroll
            for (int t8 = 0; t8 < 2; ++t8)
                sts_split8(smem, aBase, wb + t8 * 16, v + 8 * t8);
        }
        GBAR();

        l1_chunk<6>(acc, aBH, aBL, b1H, b1L, 8 * 32);
        GBAR();

        // ---------- epilogue 1: bias + relu + split -> h1 into A buffers ----------
        #pragma unroll
        for (int mb = 0; mb < 2; ++mb) {
            const int r0 = mb * 16 + (lane >> 2);
            #pragma unroll
            for (int nbl = 0; nbl < 4; ++nbl) {
                const int n0 = nq * 32 + nbl * 8 + 2 * (lane & 3);
                const float bb0 = b1s[n0], bb1 = b1s[n0 + 1];
                float f0 = fmaxf(acc[mb][nbl][0] + bb0, 0.f);
                float f1 = fmaxf(acc[mb][nbl][1] + bb1, 0.f);
                u32 hp, lp;
                splitp(f0, f1, hp, lp);
                *(u32*)(smem + aBase + r0 * STA + n0 * 2) = hp;
                *(u32*)(smem + aBase + A_PART + r0 * STA + n0 * 2) = lp;
                f0 = fmaxf(acc[mb][nbl][2] + bb0, 0.f);
                f1 = fmaxf(acc[mb][nbl][3] + bb1, 0.f);
                splitp(f0, f1, hp, lp);
                *(u32*)(smem + aBase + (r0 + 8) * STA + n0 * 2) = hp;
                *(u32*)(smem + aBase + A_PART + (r0 + 8) * STA + n0 * 2) = lp;
            }
        }

        // ---------- prefetch next tile's chunk0 ----------
        {
            const int tn = tile + gridDim.x * 4;
            if (tn < ntiles) {
                const int eg2 = tn * TILE_E + gm;
                ve = eg2 < E;
                sN = ve ? src[eg2] : 0;
                dN = ve ? dst[eg2] : 0;
                const float4* p = (const float4*)((gq < 2) ? (x + (size_t)sN * 64 + gq * 32)
                                                           : (x + (size_t)dN * 64 + (gq - 2) * 32));
                #pragma unroll
                for (int i = 0; i < 8; ++i) rc0[i] = p[i];
            }
        }
        GBAR();

        // ---------- layer 2: h1[32x128] @ W2^T -> h2[32x32]; warp owns 32r x 8c ----------
        float acc2[2][4], acc2c[2][4];
        #pragma unroll
        for (int i = 0; i < 2; ++i)
            #pragma unroll
            for (int p = 0; p < 4; ++p) { acc2[i][p] = 0.f; acc2c[i][p] = 0.f; }

        #pragma unroll
        for (int ks = 0; ks < 8; ++ks) {
            u32 ah[2][4], al[2][4], bh[2], bl[2];
            #pragma unroll
            for (int mb = 0; mb < 2; ++mb) {
                ldm4(aBH + mb * (16 * STA) + ks * 32, ah[mb]);
                ldm4(aBL + mb * (16 * STA) + ks * 32, al[mb]);
            }
            ldm2(b2H + ks * 32, bh);
            ldm2(b2L + ks * 32, bl);
            #pragma unroll
            for (int mb = 0; mb < 2; ++mb) mma_bf16(acc2[mb],  ah[mb], bh[0], bh[1]);
            #pragma unroll
            for (int mb = 0; mb < 2; ++mb) mma_bf16(acc2c[mb], al[mb], bh[0], bh[1]);
            #pragma unroll
            for (int mb = 0; mb < 2; ++mb) mma_bf16(acc2c[mb], ah[mb], bl[0], bl[1]);
        }

        // ---------- epilogue 2: bias + relu -> h2s ----------
        #pragma unroll
        for (int mb = 0; mb < 2; ++mb) {
            const int r0 = mb * 16 + (lane >> 2);
            const int c0 = nq * 8 + 2 * (lane & 3);
            const float bb0 = b2s[c0], bb1 = b2s[c0 + 1];
            *(float2*)(h2s + r0 * 34 + c0) =
                make_float2(fmaxf(acc2[mb][0] + acc2c[mb][0] + bb0, 0.f),
                            fmaxf(acc2[mb][1] + acc2c[mb][1] + bb1, 0.f));
            *(float2*)(h2s + (r0 + 8) * 34 + c0) =
                make_float2(fmaxf(acc2[mb][2] + acc2c[mb][2] + bb0, 0.f),
                            fmaxf(acc2[mb][3] + acc2c[mb][3] + bb1, 0.f));
        }
        GBAR();

        // ---------- layer 3: h2[32x32] @ W3^T + b3 -> out ----------
        if (gt < TILE_E * 2) {
            const int row = gt >> 1, cls = gt & 1;
            float sum = b3s[cls];
            #pragma unroll
            for (int k = 0; k < 32; ++k)
                sum = fmaf(h2s[row * 34 + k], W3s[cls * 32 + k], sum);
            const int ego = ebase + row;
            if (ego < E) out[(size_t)ego * 2 + cls] = sum;
        }
        // no trailing barrier: next iteration's A STS conflicts only with layer-2
        // reads, ordered by the barrier above; h2s is rewritten only after the
        // next epilogue-2 (multiple group barriers away).
    }
    #undef GBAR
}

extern "C" void kernel_launch(void* const* d_in, const int* in_sizes, int n_in,
                              void* d_out, int out_size) {
    const float* x     = (const float*)d_in[0];
    const float* efeat = (const float*)d_in[1];
    const float* nodef = (const float*)d_in[2];
    const float* edgef = (const float*)d_in[3];
    const int*   src   = (const int*)d_in[4];
    const int*   dst   = (const int*)d_in[5];
    const float* W1    = (const float*)d_in[6];
    const float* b1    = (const float*)d_in[7];
    const float* W2    = (const float*)d_in[8];
    const float* b2    = (const float*)d_in[9];
    const float* W3    = (const float*)d_in[10];
    const float* b3    = (const float*)d_in[11];
    float* out = (float*)d_out;

    const int E      = in_sizes[4];
    const int ntiles = (E + TILE_E - 1) / TILE_E;

    cudaFuncSetAttribute(edge_mlp_hmma, cudaFuncAttributeMaxDynamicSharedMemorySize, SMEM_SZ);
    int grid = 152;
    const int need = (ntiles + 3) / 4;
    if (grid > need) grid = need;
    edge_mlp_hmma<<<grid, NTHR, SMEM_SZ>>>(x, efeat, nodef, edgef, src, dst,
                                           W1, b1, W2, b2, W3, b3, out, E, ntiles);
}

// round 14
// speedup vs baseline: 1.0319x; 1.0319x over previous
#include <cuda_runtime.h>
#include <cuda_bf16.h>
#include <cstdint>

typedef uint32_t u32;
typedef unsigned short u16;

#define NTHR   256
#define TILE_E 32          // per group (4 groups x 2 warps)
#define K1     214

#define STA  272           // A/h1 row stride bytes (136 bf16)
#define STW1 464           // W1 row stride (232 bf16)
#define STW2 272

#define A_PART   8704      // 32 rows * STA
#define OFF_B1S  0
#define OFF_B2S  512
#define OFF_W3S  640
#define OFF_B3S  896
#define OFF_A0   1024      // group g A: hi at OFF_A0+g*2*A_PART, lo at +A_PART
#define OFF_W1H  (OFF_A0 + 8 * A_PART)          // 70656
#define OFF_W1L  (OFF_W1H + 128 * STW1)         // 130048
#define OFF_W2H  (OFF_W1L + 128 * STW1)         // 189440
#define OFF_W2L  (OFF_W2H + 32 * STW2)          // 198144
#define OFF_H2   (OFF_W2L + 32 * STW2)          // 206848; per group +4352
#define SMEM_SZ  (OFF_H2 + 4 * 32 * 34 * 4)     // 224256 B

__device__ __forceinline__ u32 s2u(const void* p) {
    u32 a;
    asm("{ .reg .u64 t; cvta.to.shared.u64 t, %1; cvt.u32.u64 %0, t; }" : "=r"(a) : "l"(p));
    return a;
}
__device__ __forceinline__ void ldm4(u32 addr, u32* r) {
    asm volatile("ldmatrix.sync.aligned.m8n8.x4.shared.b16 {%0,%1,%2,%3}, [%4];"
                 : "=r"(r[0]), "=r"(r[1]), "=r"(r[2]), "=r"(r[3]) : "r"(addr));
}
__device__ __forceinline__ void mma_bf16(float* c, const u32* a, u32 b0, u32 b1) {
    asm volatile("mma.sync.aligned.m16n8k16.row.col.f32.bf16.bf16.f32 "
                 "{%0,%1,%2,%3}, {%4,%5,%6,%7}, {%8,%9}, {%0,%1,%2,%3};"
                 : "+f"(c[0]), "+f"(c[1]), "+f"(c[2]), "+f"(c[3])
                 : "r"(a[0]), "r"(a[1]), "r"(a[2]), "r"(a[3]), "r"(b0), "r"(b1));
}
__device__ __forceinline__ u32 cvt2(float a, float b) {
    u32 r;
    asm("cvt.rn.bf16x2.f32 %0, %2, %1;" : "=r"(r) : "f"(a), "f"(b));
    return r;
}
__device__ __forceinline__ void splitp(float a, float b, u32& hp, u32& lp) {
    u32 ua = __float_as_uint(a), ub = __float_as_uint(b);
    hp = __byte_perm(ua, ub, 0x7632);
    float ra = a - __uint_as_float(ua & 0xFFFF0000u);
    float rb = b - __uint_as_float(ub & 0xFFFF0000u);
    lp = cvt2(ra, rb);
}
// split 8 floats and store 16B hi at base+wb, 16B lo at base+A_PART+wb
__device__ __forceinline__ void sts_split8(char* smem, u32 base, u32 wb, const float* v) {
    uint4 hv, lv;
    splitp(v[0], v[1], hv.x, lv.x);
    splitp(v[2], v[3], hv.y, lv.y);
    splitp(v[4], v[5], hv.z, lv.z);
    splitp(v[6], v[7], hv.w, lv.w);
    *(uint4*)(smem + base + wb) = hv;
    *(uint4*)(smem + base + A_PART + wb) = lv;
}

// layer-1 chunk, term-outer ordering; warp tile 32 rows x 64 cols
template <int NKS>
__device__ __forceinline__ void l1_chunk(float (&acc)[2][8][4],
                                         u32 aBH, u32 aBL,
                                         u32 b1H, u32 b1L, u32 bk)
{
    #pragma unroll
    for (int ks = 0; ks < NKS; ++ks) {
        u32 ah[2][4], al[2][4], bh[4][4], bl[4][4];
        #pragma unroll
        for (int mb = 0; mb < 2; ++mb) {
            ldm4(aBH + mb * (16 * STA) + ks * 32, ah[mb]);
            ldm4(aBL + mb * (16 * STA) + ks * 32, al[mb]);
        }
        #pragma unroll
        for (int np = 0; np < 4; ++np) {
            ldm4(b1H + np * (16 * STW1) + bk + ks * 32, bh[np]);
            ldm4(b1L + np * (16 * STW1) + bk + ks * 32, bl[np]);
        }
        // term 1: Ah*Bh (16 independent MMAs)
        #pragma unroll
        for (int np = 0; np < 4; ++np)
            #pragma unroll
            for (int mb = 0; mb < 2; ++mb) {
                mma_bf16(acc[mb][2 * np],     ah[mb], bh[np][0], bh[np][1]);
                mma_bf16(acc[mb][2 * np + 1], ah[mb], bh[np][2], bh[np][3]);
            }
        // term 2: Al*Bh
        #pragma unroll
        for (int np = 0; np < 4; ++np)
            #pragma unroll
            for (int mb = 0; mb < 2; ++mb) {
                mma_bf16(acc[mb][2 * np],     al[mb], bh[np][0], bh[np][1]);
                mma_bf16(acc[mb][2 * np + 1], al[mb], bh[np][2], bh[np][3]);
            }
        // term 3: Ah*Bl
        #pragma unroll
        for (int np = 0; np < 4; ++np)
            #pragma unroll
            for (int mb = 0; mb < 2; ++mb) {
                mma_bf16(acc[mb][2 * np],     ah[mb], bl[np][0], bl[np][1]);
                mma_bf16(acc[mb][2 * np + 1], ah[mb], bl[np][2], bl[np][3]);
            }
    }
}

extern "C" __global__ void __launch_bounds__(NTHR, 1)
edge_mlp_hmma(const float* __restrict__ x, const float* __restrict__ efeat,
              const float* __restrict__ nodef, const float* __restrict__ edgef,
              const int* __restrict__ src, const int* __restrict__ dst,
              const float* __restrict__ W1, const float* __restrict__ b1,
              const float* __restrict__ W2, const float* __restrict__ b2,
              const float* __restrict__ W3, const float* __restrict__ b3,
              float* __restrict__ out, int E, int ntiles)
{
    extern __shared__ char smem[];
    const u32 sb   = s2u(smem);
    const int tid  = threadIdx.x;
    const int g    = tid >> 6;          // pipeline group 0..3
    const int gt   = tid & 63;          // thread within group
    const int nh   = (gt >> 5);         // warp within group = n-half (0/1)
    const int lane = tid & 31;
    const int barid = g + 1;            // named barrier id for this group

    const u32 aBase = OFF_A0 + (u32)g * (2 * A_PART);   // hi base; lo = +A_PART

    const int gm = gt >> 1, gq = gt & 1;  // gather: 2 threads per edge (32 edges)

    // ---------- initial prefetch: this group's tile-0 chunk0 ----------
    int sN, dN;
    bool ve;
    float4 rc0[16];
    {
        const int eg = (blockIdx.x * 4 + g) * TILE_E + gm;
        ve = eg < E;
        sN = ve ? src[eg] : 0;
        dN = ve ? dst[eg] : 0;
        const float4* p = (const float4*)(x + (size_t)(gq ? dN : sN) * 64);
        #pragma unroll
        for (int i = 0; i < 16; ++i) rc0[i] = p[i];
    }

    // ---------- one-time weight staging (whole block) ----------
    for (int i = tid; i < 128 * 232; i += NTHR) {
        const int j = i / 232, k = i - j * 232;
        const float v = (k < K1) ? W1[j * K1 + k] : 0.f;
        const u32 uv = __float_as_uint(v);
        *(u16*)(smem + OFF_W1H + j * STW1 + k * 2) = (u16)(uv >> 16);
        const float r = v - __uint_as_float(uv & 0xFFFF0000u);
        const __nv_bfloat16 rb = __float2bfloat16(r);
        *(u16*)(smem + OFF_W1L + j * STW1 + k * 2) = *(const u16*)&rb;
    }
    for (int i = tid; i < 32 * 136; i += NTHR) {
        const int j = i / 136, k = i - j * 136;
        const float v = (k < 128) ? W2[j * 128 + k] : 0.f;
        const u32 uv = __float_as_uint(v);
        *(u16*)(smem + OFF_W2H + j * STW2 + k * 2) = (u16)(uv >> 16);
        const float r = v - __uint_as_float(uv & 0xFFFF0000u);
        const __nv_bfloat16 rb = __float2bfloat16(r);
        *(u16*)(smem + OFF_W2L + j * STW2 + k * 2) = *(const u16*)&rb;
    }
    if (tid < 128) ((float*)(smem + OFF_B1S))[tid] = b1[tid];
    if (tid < 32)  ((float*)(smem + OFF_B2S))[tid] = b2[tid];
    if (tid < 64)  ((float*)(smem + OFF_W3S))[tid] = W3[tid];
    if (tid < 2)   ((float*)(smem + OFF_B3S))[tid] = b3[tid];

    // ---------- per-lane fragment addresses (group-local; warp = n-half) ----------
    const int aRow = ((lane >> 3) & 1) * 8 + (lane & 7);
    const u32 aOff = (u32)aRow * STA + (u32)(lane >> 4) * 16;
    const u32 aBH  = sb + aBase + aOff;
    const u32 aBL  = aBH + A_PART;
    const int bSel = lane >> 4, bKh = (lane >> 3) & 1, bRow = lane & 7;
    const u32 b1off = (u32)(nh * 64 + bSel * 8 + bRow) * STW1 + (u32)bKh * 16;
    const u32 b1H  = sb + OFF_W1H + b1off;
    const u32 b1L  = sb + OFF_W1L + b1off;
    const u32 b2off = (u32)(nh * 16 + bSel * 8 + bRow) * STW2 + (u32)bKh * 16;
    const u32 b2H  = sb + OFF_W2H + b2off;
    const u32 b2L  = sb + OFF_W2L + b2off;

    const float* b1s = (const float*)(smem + OFF_B1S);
    const float* b2s = (const float*)(smem + OFF_B2S);
    const float* W3s = (const float*)(smem + OFF_W3S);
    const float* b3s = (const float*)(smem + OFF_B3S);
    float* h2s = (float*)(smem + OFF_H2 + g * 4352);   // [32][34] f32

    __syncthreads();   // weights staged (block-wide, once)

    #define GBAR() asm volatile("bar.sync %0, %1;" :: "r"(barid), "n"(64) : "memory")

    for (int tile = blockIdx.x * 4 + g; tile < ntiles; tile += gridDim.x * 4) {
        const int ebase = tile * TILE_E;
        const int  eg   = ebase + gm;
        const size_t egc = ve ? (size_t)eg : 0;

        // ---------- STS chunk0 from prefetched registers (64 cols/thread) ----------
        {
            const float* v = (const float*)rc0;
            const u32 wb = (u32)gm * STA + (u32)gq * 128;
            #pragma unroll
            for (int t8 = 0; t8 < 8; ++t8)
                sts_split8(smem, aBase, wb + t8 * 16, v + 8 * t8);
        }

        // ---------- prefetch chunk1 -> registers (covered by chunk0 MMA) ----------
        float4 e4[8];
        float  ns[16];
        {
            const float4* p = (const float4*)(efeat + egc * 64) + gq * 8;
            #pragma unroll
            for (int i = 0; i < 8; ++i) e4[i] = p[i];
            if (gq == 0) {
                #pragma unroll
                for (int j = 0; j < 10; ++j) ns[j] = nodef[(size_t)sN * 10 + j];
                #pragma unroll
                for (int j = 0; j < 6; ++j)  ns[10 + j] = nodef[(size_t)dN * 10 + j];
            } else {
                #pragma unroll
                for (int j = 0; j < 4; ++j) ns[j] = nodef[(size_t)dN * 10 + 6 + j];
                ns[4] = edgef[egc * 2];
                ns[5] = edgef[egc * 2 + 1];
                #pragma unroll
                for (int j = 6; j < 16; ++j) ns[j] = 0.f;
            }
        }
        GBAR();

        float acc[2][8][4];
        #pragma unroll
        for (int i = 0; i < 2; ++i)
            #pragma unroll
            for (int j = 0; j < 8; ++j)
                #pragma unroll
                for (int p = 0; p < 4; ++p) acc[i][j][p] = 0.f;

        l1_chunk<8>(acc, aBH, aBL, b1H, b1L, 0);
        GBAR();

        // ---------- STS chunk1 (A cols 0..95 reused for k=128..223) ----------
        {
            // e part: gq=0 -> cols 0..31, gq=1 -> cols 32..63
            const float* v = (const float*)e4;
            const u32 wb = (u32)gm * STA + (u32)gq * 64;
            #pragma unroll
            for (int t8 = 0; t8 < 4; ++t8)
                sts_split8(smem, aBase, wb + t8 * 16, v + 8 * t8);
            // nf/ef part: gq=0 -> cols 64..79, gq=1 -> cols 80..95
            const u32 wb2 = (u32)gm * STA + 128 + (u32)gq * 32;
            sts_split8(smem, aBase, wb2,      ns);
            sts_split8(smem, aBase, wb2 + 16, ns + 8);
        }
        GBAR();

        l1_chunk<6>(acc, aBH, aBL, b1H, b1L, 8 * 32);
        GBAR();

        // ---------- epilogue 1: bias + relu + split -> h1 into A buffers ----------
        #pragma unroll
        for (int mb = 0; mb < 2; ++mb) {
            const int r0 = mb * 16 + (lane >> 2);
            #pragma unroll
            for (int nbl = 0; nbl < 8; ++nbl) {
                const int n0 = nh * 64 + nbl * 8 + 2 * (lane & 3);
                const float bb0 = b1s[n0], bb1 = b1s[n0 + 1];
                float f0 = fmaxf(acc[mb][nbl][0] + bb0, 0.f);
                float f1 = fmaxf(acc[mb][nbl][1] + bb1, 0.f);
                u32 hp, lp;
                splitp(f0, f1, hp, lp);
                *(u32*)(smem + aBase + r0 * STA + n0 * 2) = hp;
                *(u32*)(smem + aBase + A_PART + r0 * STA + n0 * 2) = lp;
                f0 = fmaxf(acc[mb][nbl][2] + bb0, 0.f);
                f1 = fmaxf(acc[mb][nbl][3] + bb1, 0.f);
                splitp(f0, f1, hp, lp);
                *(u32*)(smem + aBase + (r0 + 8) * STA + n0 * 2) = hp;
                *(u32*)(smem + aBase + A_PART + (r0 + 8) * STA + n0 * 2) = lp;
            }
        }

        // ---------- prefetch next tile's chunk0 (covered by layer2/3) ----------
        {
            const int tn = tile + gridDim.x * 4;
            if (tn < ntiles) {
                const int eg2 = tn * TILE_E + gm;
                ve = eg2 < E;
                sN = ve ? src[eg2] : 0;
                dN = ve ? dst[eg2] : 0;
                const float4* p = (const float4*)(x + (size_t)(gq ? dN : sN) * 64);
                #pragma unroll
                for (int i = 0; i < 16; ++i) rc0[i] = p[i];
            }
        }
        GBAR();

        // ---------- layer 2: h1[32x128] @ W2^T -> h2[32x32]; warp owns 32r x 16c ----------
        float acc2[2][2][4], acc2c[2][2][4];
        #pragma unroll
        for (int i = 0; i < 2; ++i)
            #pragma unroll
            for (int j = 0; j < 2; ++j)
                #pragma unroll
                for (int p = 0; p < 4; ++p) { acc2[i][j][p] = 0.f; acc2c[i][j][p] = 0.f; }

        #pragma unroll
        for (int ks = 0; ks < 8; ++ks) {
            u32 ah[2][4], al[2][4], bh[4], bl[4];
            #pragma unroll
            for (int mb = 0; mb < 2; ++mb) {
                ldm4(aBH + mb * (16 * STA) + ks * 32, ah[mb]);
                ldm4(aBL + mb * (16 * STA) + ks * 32, al[mb]);
            }
            ldm4(b2H + ks * 32, bh);
            ldm4(b2L + ks * 32, bl);
            #pragma unroll
            for (int mb = 0; mb < 2; ++mb) {
                mma_bf16(acc2[mb][0],  ah[mb], bh[0], bh[1]);
                mma_bf16(acc2[mb][1],  ah[mb], bh[2], bh[3]);
            }
            #pragma unroll
            for (int mb = 0; mb < 2; ++mb) {
                mma_bf16(acc2c[mb][0], al[mb], bh[0], bh[1]);
                mma_bf16(acc2c[mb][1], al[mb], bh[2], bh[3]);
            }
            #pragma unroll
            for (int mb = 0; mb < 2; ++mb) {
                mma_bf16(acc2c[mb][0], ah[mb], bl[0], bl[1]);
                mma_bf16(acc2c[mb][1], ah[mb], bl[2], bl[3]);
            }
        }

        // ---------- epilogue 2: bias + relu -> h2s ----------
        #pragma unroll
        for (int mb = 0; mb < 2; ++mb) {
            const int r0 = mb * 16 + (lane >> 2);
            #pragma unroll
            for (int nbl = 0; nbl < 2; ++nbl) {
                const int c0 = nh * 16 + nbl * 8 + 2 * (lane & 3);
                const float bb0 = b2s[c0], bb1 = b2s[c0 + 1];
                *(float2*)(h2s + r0 * 34 + c0) =
                    make_float2(fmaxf(acc2[mb][nbl][0] + acc2c[mb][nbl][0] + bb0, 0.f),
                                fmaxf(acc2[mb][nbl][1] + acc2c[mb][nbl][1] + bb1, 0.f));
                *(float2*)(h2s + (r0 + 8) * 34 + c0) =
                    make_float2(fmaxf(acc2[mb][nbl][2] + acc2c[mb][nbl][2] + bb0, 0.f),
                                fmaxf(acc2[mb][nbl][3] + acc2c[mb][nbl][3] + bb1, 0.f));
            }
        }
        GBAR();

        // ---------- layer 3: h2[32x32] @ W3^T + b3 -> out (64 threads = 32e x 2cls) ----------
        {
            const int row = gt >> 1, cls = gt & 1;
            float sum = b3s[cls];
            #pragma unroll
            for (int k = 0; k < 32; ++k)
                sum = fmaf(h2s[row * 34 + k], W3s[cls * 32 + k], sum);
            const int ego = ebase + row;
            if (ego < E) out[(size_t)ego * 2 + cls] = sum;
        }
        // no trailing barrier: next iteration's A STS conflicts only with layer-2
        // reads, ordered by the barrier above; h2s is rewritten only after the
        // next epilogue-2 (multiple group barriers away).
    }
    #undef GBAR
}

extern "C" void kernel_launch(void* const* d_in, const int* in_sizes, int n_in,
                              void* d_out, int out_size) {
    const float* x     = (const float*)d_in[0];
    const float* efeat = (const float*)d_in[1];
    const float* nodef = (const float*)d_in[2];
    const float* edgef = (const float*)d_in[3];
    const int*   src   = (const int*)d_in[4];
    const int*   dst   = (const int*)d_in[5];
    const float* W1    = (const float*)d_in[6];
    const float* b1    = (const float*)d_in[7];
    const float* W2    = (const float*)d_in[8];
    const float* b2    = (const float*)d_in[9];
    const float* W3    = (const float*)d_in[10];
    const float* b3    = (const float*)d_in[11];
    float* out = (float*)d_out;

    const int E      = in_sizes[4];
    const int ntiles = (E + TILE_E - 1) / TILE_E;

    cudaFuncSetAttribute(edge_mlp_hmma, cudaFuncAttributeMaxDynamicSharedMemorySize, SMEM_SZ);
    int grid = 152;
    const int need = (ntiles + 3) / 4;
    if (grid > need) grid = need;
    edge_mlp_hmma<<<grid, NTHR, SMEM_SZ>>>(x, efeat, nodef, edgef, src, dst,
                                           W1, b1, W2, b2, W3, b3, out, E, ntiles);
}

// round 15
// speedup vs baseline: 1.0538x; 1.0212x over previous
#include <cuda_runtime.h>
#include <cuda_bf16.h>
#include <cstdint>

typedef uint32_t u32;
typedef unsigned short u16;

#define NTHR   384
#define TILE_E 32          // per group (4 groups x [2 MMA warps + 1 IO warp])
#define K1     214

#define STA  272           // A/h1 row stride bytes (136 bf16)
#define STW1 464           // W1 row stride (232 bf16)
#define STW2 272

#define A_PART   8704      // 32 rows * STA
#define OFF_B1S  0
#define OFF_B2S  512
#define OFF_W3S  640
#define OFF_B3S  896
#define OFF_A0   1024      // group g A: hi at OFF_A0+g*2*A_PART, lo at +A_PART
#define OFF_W1H  (OFF_A0 + 8 * A_PART)          // 70656
#define OFF_W1L  (OFF_W1H + 128 * STW1)         // 130048
#define OFF_W2H  (OFF_W1L + 128 * STW1)         // 189440
#define OFF_W2L  (OFF_W2H + 32 * STW2)          // 198144
#define OFF_H2   (OFF_W2L + 32 * STW2)          // 206848; per group +4352
#define SMEM_SZ  (OFF_H2 + 4 * 32 * 34 * 4)     // 224256 B

__device__ __forceinline__ u32 s2u(const void* p) {
    u32 a;
    asm("{ .reg .u64 t; cvta.to.shared.u64 t, %1; cvt.u32.u64 %0, t; }" : "=r"(a) : "l"(p));
    return a;
}
__device__ __forceinline__ void ldm4(u32 addr, u32* r) {
    asm volatile("ldmatrix.sync.aligned.m8n8.x4.shared.b16 {%0,%1,%2,%3}, [%4];"
                 : "=r"(r[0]), "=r"(r[1]), "=r"(r[2]), "=r"(r[3]) : "r"(addr));
}
__device__ __forceinline__ void mma_bf16(float* c, const u32* a, u32 b0, u32 b1) {
    asm volatile("mma.sync.aligned.m16n8k16.row.col.f32.bf16.bf16.f32 "
                 "{%0,%1,%2,%3}, {%4,%5,%6,%7}, {%8,%9}, {%0,%1,%2,%3};"
                 : "+f"(c[0]), "+f"(c[1]), "+f"(c[2]), "+f"(c[3])
                 : "r"(a[0]), "r"(a[1]), "r"(a[2]), "r"(a[3]), "r"(b0), "r"(b1));
}
__device__ __forceinline__ u32 cvt2(float a, float b) {
    u32 r;
    asm("cvt.rn.bf16x2.f32 %0, %2, %1;" : "=r"(r) : "f"(a), "f"(b));
    return r;
}
__device__ __forceinline__ void splitp(float a, float b, u32& hp, u32& lp) {
    u32 ua = __float_as_uint(a), ub = __float_as_uint(b);
    hp = __byte_perm(ua, ub, 0x7632);
    float ra = a - __uint_as_float(ua & 0xFFFF0000u);
    float rb = b - __uint_as_float(ub & 0xFFFF0000u);
    lp = cvt2(ra, rb);
}
// split 8 floats and store 16B hi at base+wb, 16B lo at base+A_PART+wb
__device__ __forceinline__ void sts_split8(char* smem, u32 base, u32 wb, const float* v) {
    uint4 hv, lv;
    splitp(v[0], v[1], hv.x, lv.x);
    splitp(v[2], v[3], hv.y, lv.y);
    splitp(v[4], v[5], hv.z, lv.z);
    splitp(v[6], v[7], hv.w, lv.w);
    *(uint4*)(smem + base + wb) = hv;
    *(uint4*)(smem + base + A_PART + wb) = lv;
}

// layer-1 chunk, term-outer ordering; warp tile 32 rows x 64 cols
template <int NKS>
__device__ __forceinline__ void l1_chunk(float (&acc)[2][8][4],
                                         u32 aBH, u32 aBL,
                                         u32 b1H, u32 b1L, u32 bk)
{
    #pragma unroll
    for (int ks = 0; ks < NKS; ++ks) {
        u32 ah[2][4], al[2][4], bh[4][4], bl[4][4];
        #pragma unroll
        for (int mb = 0; mb < 2; ++mb) {
            ldm4(aBH + mb * (16 * STA) + ks * 32, ah[mb]);
            ldm4(aBL + mb * (16 * STA) + ks * 32, al[mb]);
        }
        #pragma unroll
        for (int np = 0; np < 4; ++np) {
            ldm4(b1H + np * (16 * STW1) + bk + ks * 32, bh[np]);
            ldm4(b1L + np * (16 * STW1) + bk + ks * 32, bl[np]);
        }
        #pragma unroll
        for (int np = 0; np < 4; ++np)
            #pragma unroll
            for (int mb = 0; mb < 2; ++mb) {
                mma_bf16(acc[mb][2 * np],     ah[mb], bh[np][0], bh[np][1]);
                mma_bf16(acc[mb][2 * np + 1], ah[mb], bh[np][2], bh[np][3]);
            }
        #pragma unroll
        for (int np = 0; np < 4; ++np)
            #pragma unroll
            for (int mb = 0; mb < 2; ++mb) {
                mma_bf16(acc[mb][2 * np],     al[mb], bh[np][0], bh[np][1]);
                mma_bf16(acc[mb][2 * np + 1], al[mb], bh[np][2], bh[np][3]);
            }
        #pragma unroll
        for (int np = 0; np < 4; ++np)
            #pragma unroll
            for (int mb = 0; mb < 2; ++mb) {
                mma_bf16(acc[mb][2 * np],     ah[mb], bl[np][0], bl[np][1]);
                mma_bf16(acc[mb][2 * np + 1], ah[mb], bl[np][2], bl[np][3]);
            }
    }
}

extern "C" __global__ void __launch_bounds__(NTHR, 1)
edge_mlp_hmma(const float* __restrict__ x, const float* __restrict__ efeat,
              const float* __restrict__ nodef, const float* __restrict__ edgef,
              const int* __restrict__ src, const int* __restrict__ dst,
              const float* __restrict__ W1, const float* __restrict__ b1,
              const float* __restrict__ W2, const float* __restrict__ b2,
              const float* __restrict__ W3, const float* __restrict__ b3,
              float* __restrict__ out, int E, int ntiles)
{
    extern __shared__ char smem[];
    const u32 sb   = s2u(smem);
    const int tid  = threadIdx.x;
    const int g    = tid / 96;          // pipeline group 0..3
    const int gt   = tid - g * 96;      // thread within group
    const int lane = tid & 31;
    const int bar96 = 1 + g;            // group-wide barrier (96 threads)
    const int bar64 = 5 + g;            // MMA-warps-only barrier (64 threads)

    const u32 aBase = OFF_A0 + (u32)g * (2 * A_PART);   // hi base; lo = +A_PART

    // ---------- one-time weight staging (whole block) ----------
    for (int i = tid; i < 128 * 232; i += NTHR) {
        const int j = i / 232, k = i - j * 232;
        const float v = (k < K1) ? W1[j * K1 + k] : 0.f;
        const u32 uv = __float_as_uint(v);
        *(u16*)(smem + OFF_W1H + j * STW1 + k * 2) = (u16)(uv >> 16);
        const float r = v - __uint_as_float(uv & 0xFFFF0000u);
        const __nv_bfloat16 rb = __float2bfloat16(r);
        *(u16*)(smem + OFF_W1L + j * STW1 + k * 2) = *(const u16*)&rb;
    }
    for (int i = tid; i < 32 * 136; i += NTHR) {
        const int j = i / 136, k = i - j * 136;
        const float v = (k < 128) ? W2[j * 128 + k] : 0.f;
        const u32 uv = __float_as_uint(v);
        *(u16*)(smem + OFF_W2H + j * STW2 + k * 2) = (u16)(uv >> 16);
        const float r = v - __uint_as_float(uv & 0xFFFF0000u);
        const __nv_bfloat16 rb = __float2bfloat16(r);
        *(u16*)(smem + OFF_W2L + j * STW2 + k * 2) = *(const u16*)&rb;
    }
    if (tid < 128) ((float*)(smem + OFF_B1S))[tid] = b1[tid];
    if (tid < 32)  ((float*)(smem + OFF_B2S))[tid] = b2[tid];
    if (tid < 64)  ((float*)(smem + OFF_W3S))[tid] = W3[tid];
    if (tid < 2)   ((float*)(smem + OFF_B3S))[tid] = b3[tid];

    const float* b1s = (const float*)(smem + OFF_B1S);
    const float* b2s = (const float*)(smem + OFF_B2S);
    const float* W3s = (const float*)(smem + OFF_W3S);
    const float* b3s = (const float*)(smem + OFF_B3S);
    float* h2s = (float*)(smem + OFF_H2 + g * 4352);   // [32][34] f32

    __syncthreads();   // weights staged (block-wide, once)

    #define GBAR96() asm volatile("bar.sync %0, %1;" :: "r"(bar96), "n"(96) : "memory")
    #define GBAR64() asm volatile("bar.sync %0, %1;" :: "r"(bar64), "n"(64) : "memory")

    const int tile0 = blockIdx.x * 4 + g;
    const int tstep = gridDim.x * 4;

    if (gt >= 64) {
        // ================= IO warp: gathers, splits, STS, prefetch =================
        const int iolane = gt - 64;   // edge within tile

        int sN = 0, dN = 0;
        bool ve = false;
        float4 c0s[16], c0d[16];      // raw x[src], x[dst] rows (128 regs)
        if (tile0 < ntiles) {
            const int eg = tile0 * TILE_E + iolane;
            ve = eg < E;
            sN = ve ? src[eg] : 0;
            dN = ve ? dst[eg] : 0;
            const float4* ps = (const float4*)(x + (size_t)sN * 64);
            const float4* pd = (const float4*)(x + (size_t)dN * 64);
            #pragma unroll
            for (int i = 0; i < 16; ++i) { c0s[i] = ps[i]; c0d[i] = pd[i]; }
        }

        const u32 wb = (u32)iolane * STA;

        for (int tile = tile0; tile < ntiles; tile += tstep) {
            const int eg = tile * TILE_E + iolane;
            const size_t egc = ve ? (size_t)eg : 0;

            // ---- STS chunk0 (split on the fly); MMA warps run layer-3(prev) ----
            #pragma unroll
            for (int t8 = 0; t8 < 8; ++t8)
                sts_split8(smem, aBase, wb + t8 * 16, ((const float*)c0s) + 8 * t8);
            #pragma unroll
            for (int t8 = 0; t8 < 8; ++t8)
                sts_split8(smem, aBase, wb + 128 + t8 * 16, ((const float*)c0d) + 8 * t8);
            GBAR96();   // B1: c0 ready

            // ---- gather chunk1 raw (covered by MMA chunk0) ----
            float4 e4[16];
            float  ns[32];
            {
                const float4* pe = (const float4*)(efeat + egc * 64);
                #pragma unroll
                for (int i = 0; i < 16; ++i) e4[i] = pe[i];
                #pragma unroll
                for (int j = 0; j < 10; ++j) {
                    ns[j]      = nodef[(size_t)sN * 10 + j];
                    ns[10 + j] = nodef[(size_t)dN * 10 + j];
                }
                ns[20] = edgef[egc * 2];
                ns[21] = edgef[egc * 2 + 1];
                #pragma unroll
                for (int j = 22; j < 32; ++j) ns[j] = 0.f;
            }
            GBAR96();   // B2: MMA done reading chunk0 cols

            // ---- STS chunk1 (cols 0..95) ----
            #pragma unroll
            for (int t8 = 0; t8 < 8; ++t8)
                sts_split8(smem, aBase, wb + t8 * 16, ((const float*)e4) + 8 * t8);
            #pragma unroll
            for (int t4 = 0; t4 < 4; ++t4)
                sts_split8(smem, aBase, wb + 128 + t4 * 16, ns + 8 * t4);
            GBAR96();   // B3: c1 ready

            // ---- prefetch next tile's chunk0 (covered by chunk<6>+epi+l2) ----
            {
                const int tn = tile + tstep;
                if (tn < ntiles) {
                    const int eg2 = tn * TILE_E + iolane;
                    ve = eg2 < E;
                    sN = ve ? src[eg2] : 0;
                    dN = ve ? dst[eg2] : 0;
                    const float4* ps = (const float4*)(x + (size_t)sN * 64);
                    const float4* pd = (const float4*)(x + (size_t)dN * 64);
                    #pragma unroll
                    for (int i = 0; i < 16; ++i) { c0s[i] = ps[i]; c0d[i] = pd[i]; }
                }
            }
            GBAR96();   // B6: layer-2 reads done -> A free for next STS-c0
        }
    } else {
        // ================= MMA warps: pure compute =================
        const int nh = gt >> 5;   // n-half (0/1)

        const int aRow = ((lane >> 3) & 1) * 8 + (lane & 7);
        const u32 aOff = (u32)aRow * STA + (u32)(lane >> 4) * 16;
        const u32 aBH  = sb + aBase + aOff;
        const u32 aBL  = aBH + A_PART;
        const int bSel = lane >> 4, bKh = (lane >> 3) & 1, bRow = lane & 7;
        const u32 b1off = (u32)(nh * 64 + bSel * 8 + bRow) * STW1 + (u32)bKh * 16;
        const u32 b1H  = sb + OFF_W1H + b1off;
        const u32 b1L  = sb + OFF_W1L + b1off;
        const u32 b2off = (u32)(nh * 16 + bSel * 8 + bRow) * STW2 + (u32)bKh * 16;
        const u32 b2H  = sb + OFF_W2H + b2off;
        const u32 b2L  = sb + OFF_W2L + b2off;

        int prev_ebase = -1;

        for (int tile = tile0; tile < ntiles; tile += tstep) {
            const int ebase = tile * TILE_E;

            // ---- layer 3 of previous tile (overlaps IO's STS-c0) ----
            if (prev_ebase >= 0) {
                const int row = gt >> 1, cls = gt & 1;
                float sum = b3s[cls];
                #pragma unroll
                for (int k = 0; k < 32; ++k)
                    sum = fmaf(h2s[row * 34 + k], W3s[cls * 32 + k], sum);
                const int ego = prev_ebase + row;
                if (ego < E) out[(size_t)ego * 2 + cls] = sum;
            }
            GBAR96();   // B1: c0 ready

            float acc[2][8][4];
            #pragma unroll
            for (int i = 0; i < 2; ++i)
                #pragma unroll
                for (int j = 0; j < 8; ++j)
                    #pragma unroll
                    for (int p = 0; p < 4; ++p) acc[i][j][p] = 0.f;

            l1_chunk<8>(acc, aBH, aBL, b1H, b1L, 0);
            GBAR96();   // B2: chunk0 reads done (IO may STS c1)
            GBAR96();   // B3: c1 ready

            l1_chunk<6>(acc, aBH, aBL, b1H, b1L, 8 * 32);
            GBAR64();   // B4: both MMA warps done reading A

            // ---- epilogue 1: bias + relu + split -> h1 into A buffers ----
            #pragma unroll
            for (int mb = 0; mb < 2; ++mb) {
                const int r0 = mb * 16 + (lane >> 2);
                #pragma unroll
                for (int nbl = 0; nbl < 8; ++nbl) {
                    const int n0 = nh * 64 + nbl * 8 + 2 * (lane & 3);
                    const float bb0 = b1s[n0], bb1 = b1s[n0 + 1];
                    float f0 = fmaxf(acc[mb][nbl][0] + bb0, 0.f);
                    float f1 = fmaxf(acc[mb][nbl][1] + bb1, 0.f);
                    u32 hp, lp;
                    splitp(f0, f1, hp, lp);
                    *(u32*)(smem + aBase + r0 * STA + n0 * 2) = hp;
                    *(u32*)(smem + aBase + A_PART + r0 * STA + n0 * 2) = lp;
                    f0 = fmaxf(acc[mb][nbl][2] + bb0, 0.f);
                    f1 = fmaxf(acc[mb][nbl][3] + bb1, 0.f);
                    splitp(f0, f1, hp, lp);
                    *(u32*)(smem + aBase + (r0 + 8) * STA + n0 * 2) = hp;
                    *(u32*)(smem + aBase + A_PART + (r0 + 8) * STA + n0 * 2) = lp;
                }
            }
            GBAR64();   // B5: h1 ready

            // ---- layer 2: h1[32x128] @ W2^T -> h2[32x32]; warp owns 32r x 16c ----
            float acc2[2][2][4], acc2c[2][2][4];
            #pragma unroll
            for (int i = 0; i < 2; ++i)
                #pragma unroll
                for (int j = 0; j < 2; ++j)
                    #pragma unroll
                    for (int p = 0; p < 4; ++p) { acc2[i][j][p] = 0.f; acc2c[i][j][p] = 0.f; }

            #pragma unroll
            for (int ks = 0; ks < 8; ++ks) {
                u32 ah[2][4], al[2][4], bh[4], bl[4];
                #pragma unroll
                for (int mb = 0; mb < 2; ++mb) {
                    ldm4(aBH + mb * (16 * STA) + ks * 32, ah[mb]);
                    ldm4(aBL + mb * (16 * STA) + ks * 32, al[mb]);
                }
                ldm4(b2H + ks * 32, bh);
                ldm4(b2L + ks * 32, bl);
                #pragma unroll
                for (int mb = 0; mb < 2; ++mb) {
                    mma_bf16(acc2[mb][0],  ah[mb], bh[0], bh[1]);
                    mma_bf16(acc2[mb][1],  ah[mb], bh[2], bh[3]);
                }
                #pragma unroll
                for (int mb = 0; mb < 2; ++mb) {
                    mma_bf16(acc2c[mb][0], al[mb], bh[0], bh[1]);
                    mma_bf16(acc2c[mb][1], al[mb], bh[2], bh[3]);
                }
                #pragma unroll
                for (int mb = 0; mb < 2; ++mb) {
                    mma_bf16(acc2c[mb][0], ah[mb], bl[0], bl[1]);
                    mma_bf16(acc2c[mb][1], ah[mb], bl[2], bl[3]);
                }
            }

            // ---- epilogue 2: bias + relu -> h2s ----
            #pragma unroll
            for (int mb = 0; mb < 2; ++mb) {
                const int r0 = mb * 16 + (lane >> 2);
                #pragma unroll
                for (int nbl = 0; nbl < 2; ++nbl) {
                    const int c0 = nh * 16 + nbl * 8 + 2 * (lane & 3);
                    const float bb0 = b2s[c0], bb1 = b2s[c0 + 1];
                    *(float2*)(h2s + r0 * 34 + c0) =
                        make_float2(fmaxf(acc2[mb][nbl][0] + acc2c[mb][nbl][0] + bb0, 0.f),
                                    fmaxf(acc2[mb][nbl][1] + acc2c[mb][nbl][1] + bb1, 0.f));
                    *(float2*)(h2s + (r0 + 8) * 34 + c0) =
                        make_float2(fmaxf(acc2[mb][nbl][2] + acc2c[mb][nbl][2] + bb0, 0.f),
                                    fmaxf(acc2[mb][nbl][3] + acc2c[mb][nbl][3] + bb1, 0.f));
                }
            }
            GBAR96();   // B6: h2s ready; layer-2 A reads done (A free for IO)

            prev_ebase = ebase;
        }

        // ---- final layer 3 for the last tile ----
        if (prev_ebase >= 0) {
            const int row = gt >> 1, cls = gt & 1;
            float sum = b3s[cls];
            #pragma unroll
            for (int k = 0; k < 32; ++k)
                sum = fmaf(h2s[row * 34 + k], W3s[cls * 32 + k], sum);
            const int ego = prev_ebase + row;
            if (ego < E) out[(size_t)ego * 2 + cls] = sum;
        }
    }
    #undef GBAR96
    #undef GBAR64
}

extern "C" void kernel_launch(void* const* d_in, const int* in_sizes, int n_in,
                              void* d_out, int out_size) {
    const float* x     = (const float*)d_in[0];
    const float* efeat = (const float*)d_in[1];
    const float* nodef = (const float*)d_in[2];
    const float* edgef = (const float*)d_in[3];
    const int*   src   = (const int*)d_in[4];
    const int*   dst   = (const int*)d_in[5];
    const float* W1    = (const float*)d_in[6];
    const float* b1    = (const float*)d_in[7];
    const float* W2    = (const float*)d_in[8];
    const float* b2    = (const float*)d_in[9];
    const float* W3    = (const float*)d_in[10];
    const float* b3    = (const float*)d_in[11];
    float* out = (float*)d_out;

    const int E      = in_sizes[4];
    const int ntiles = (E + TILE_E - 1) / TILE_E;

    cudaFuncSetAttribute(edge_mlp_hmma, cudaFuncAttributeMaxDynamicSharedMemorySize, SMEM_SZ);
    int grid = 152;
    const int need = (ntiles + 3) / 4;
    if (grid > need) grid = need;
    edge_mlp_hmma<<<grid, NTHR, SMEM_SZ>>>(x, efeat, nodef, edgef, src, dst,
                                           W1, b1, W2, b2, W3, b3, out, E, ntiles);
}

// round 16
// speedup vs baseline: 1.0689x; 1.0144x over previous
#include <cuda_runtime.h>
#include <cuda_bf16.h>
#include <cstdint>

typedef uint32_t u32;
typedef unsigned short u16;

#define NTHR   384
#define TILE_E 32          // per group (4 groups x [2 MMA warps + 1 IO warp])
#define K1     214

#define STA  272           // A/h1 row stride bytes (136 bf16)
#define STW1 464           // W1 row stride (232 bf16)
#define STW2 272

#define A_PART   8704      // 32 rows * STA
#define OFF_B1S  0
#define OFF_B2S  512
#define OFF_W3S  640
#define OFF_B3S  896
#define OFF_A0   1024      // group g A: hi at OFF_A0+g*2*A_PART, lo at +A_PART
#define OFF_W1H  (OFF_A0 + 8 * A_PART)          // 70656
#define OFF_W1L  (OFF_W1H + 128 * STW1)         // 130048
#define OFF_W2H  (OFF_W1L + 128 * STW1)         // 189440
#define OFF_W2L  (OFF_W2H + 32 * STW2)          // 198144
#define OFF_H2   (OFF_W2L + 32 * STW2)          // 206848; per group +4352
#define SMEM_SZ  (OFF_H2 + 4 * 32 * 34 * 4)     // 224256 B

__device__ __forceinline__ u32 s2u(const void* p) {
    u32 a;
    asm("{ .reg .u64 t; cvta.to.shared.u64 t, %1; cvt.u32.u64 %0, t; }" : "=r"(a) : "l"(p));
    return a;
}
__device__ __forceinline__ void ldm4(u32 addr, u32* r) {
    asm volatile("ldmatrix.sync.aligned.m8n8.x4.shared.b16 {%0,%1,%2,%3}, [%4];"
                 : "=r"(r[0]), "=r"(r[1]), "=r"(r[2]), "=r"(r[3]) : "r"(addr));
}
__device__ __forceinline__ void mma_bf16(float* c, const u32* a, u32 b0, u32 b1) {
    asm volatile("mma.sync.aligned.m16n8k16.row.col.f32.bf16.bf16.f32 "
                 "{%0,%1,%2,%3}, {%4,%5,%6,%7}, {%8,%9}, {%0,%1,%2,%3};"
                 : "+f"(c[0]), "+f"(c[1]), "+f"(c[2]), "+f"(c[3])
                 : "r"(a[0]), "r"(a[1]), "r"(a[2]), "r"(a[3]), "r"(b0), "r"(b1));
}
__device__ __forceinline__ u32 cvt2(float a, float b) {
    u32 r;
    asm("cvt.rn.bf16x2.f32 %0, %2, %1;" : "=r"(r) : "f"(a), "f"(b));
    return r;
}
__device__ __forceinline__ void splitp(float a, float b, u32& hp, u32& lp) {
    u32 ua = __float_as_uint(a), ub = __float_as_uint(b);
    hp = __byte_perm(ua, ub, 0x7632);
    float ra = a - __uint_as_float(ua & 0xFFFF0000u);
    float rb = b - __uint_as_float(ub & 0xFFFF0000u);
    lp = cvt2(ra, rb);
}
// pack 8 floats into hi uint4 + lo uint4 (no store)
__device__ __forceinline__ void pack8(const float* v, uint4& hv, uint4& lv) {
    splitp(v[0], v[1], hv.x, lv.x);
    splitp(v[2], v[3], hv.y, lv.y);
    splitp(v[4], v[5], hv.z, lv.z);
    splitp(v[6], v[7], hv.w, lv.w);
}
// split 8 floats and store 16B hi at base+wb, 16B lo at base+A_PART+wb
__device__ __forceinline__ void sts_split8(char* smem, u32 base, u32 wb, const float* v) {
    uint4 hv, lv;
    pack8(v, hv, lv);
    *(uint4*)(smem + base + wb) = hv;
    *(uint4*)(smem + base + A_PART + wb) = lv;
}

// layer-1 chunk, term-outer ordering; warp tile 32 rows x 64 cols
template <int NKS>
__device__ __forceinline__ void l1_chunk(float (&acc)[2][8][4],
                                         u32 aBH, u32 aBL,
                                         u32 b1H, u32 b1L, u32 bk)
{
    #pragma unroll
    for (int ks = 0; ks < NKS; ++ks) {
        u32 ah[2][4], al[2][4], bh[4][4], bl[4][4];
        #pragma unroll
        for (int mb = 0; mb < 2; ++mb) {
            ldm4(aBH + mb * (16 * STA) + ks * 32, ah[mb]);
            ldm4(aBL + mb * (16 * STA) + ks * 32, al[mb]);
        }
        #pragma unroll
        for (int np = 0; np < 4; ++np) {
            ldm4(b1H + np * (16 * STW1) + bk + ks * 32, bh[np]);
            ldm4(b1L + np * (16 * STW1) + bk + ks * 32, bl[np]);
        }
        #pragma unroll
        for (int np = 0; np < 4; ++np)
            #pragma unroll
            for (int mb = 0; mb < 2; ++mb) {
                mma_bf16(acc[mb][2 * np],     ah[mb], bh[np][0], bh[np][1]);
                mma_bf16(acc[mb][2 * np + 1], ah[mb], bh[np][2], bh[np][3]);
            }
        #pragma unroll
        for (int np = 0; np < 4; ++np)
            #pragma unroll
            for (int mb = 0; mb < 2; ++mb) {
                mma_bf16(acc[mb][2 * np],     al[mb], bh[np][0], bh[np][1]);
                mma_bf16(acc[mb][2 * np + 1], al[mb], bh[np][2], bh[np][3]);
            }
        #pragma unroll
        for (int np = 0; np < 4; ++np)
            #pragma unroll
            for (int mb = 0; mb < 2; ++mb) {
                mma_bf16(acc[mb][2 * np],     ah[mb], bl[np][0], bl[np][1]);
                mma_bf16(acc[mb][2 * np + 1], ah[mb], bl[np][2], bl[np][3]);
            }
    }
}

extern "C" __global__ void __launch_bounds__(NTHR, 1)
edge_mlp_hmma(const float* __restrict__ x, const float* __restrict__ efeat,
              const float* __restrict__ nodef, const float* __restrict__ edgef,
              const int* __restrict__ src, const int* __restrict__ dst,
              const float* __restrict__ W1, const float* __restrict__ b1,
              const float* __restrict__ W2, const float* __restrict__ b2,
              const float* __restrict__ W3, const float* __restrict__ b3,
              float* __restrict__ out, int E, int ntiles)
{
    extern __shared__ char smem[];
    const u32 sb   = s2u(smem);
    const int tid  = threadIdx.x;
    const int g    = tid / 96;          // pipeline group 0..3
    const int gt   = tid - g * 96;      // thread within group
    const int lane = tid & 31;
    const int bar96 = 1 + g;            // group-wide barrier (96 threads)
    const int bar64 = 5 + g;            // MMA-warps-only barrier (64 threads)

    const u32 aBase = OFF_A0 + (u32)g * (2 * A_PART);   // hi base; lo = +A_PART

    // ---------- one-time weight staging (whole block) ----------
    for (int i = tid; i < 128 * 232; i += NTHR) {
        const int j = i / 232, k = i - j * 232;
        const float v = (k < K1) ? W1[j * K1 + k] : 0.f;
        const u32 uv = __float_as_uint(v);
        *(u16*)(smem + OFF_W1H + j * STW1 + k * 2) = (u16)(uv >> 16);
        const float r = v - __uint_as_float(uv & 0xFFFF0000u);
        const __nv_bfloat16 rb = __float2bfloat16(r);
        *(u16*)(smem + OFF_W1L + j * STW1 + k * 2) = *(const u16*)&rb;
    }
    for (int i = tid; i < 32 * 136; i += NTHR) {
        const int j = i / 136, k = i - j * 136;
        const float v = (k < 128) ? W2[j * 128 + k] : 0.f;
        const u32 uv = __float_as_uint(v);
        *(u16*)(smem + OFF_W2H + j * STW2 + k * 2) = (u16)(uv >> 16);
        const float r = v - __uint_as_float(uv & 0xFFFF0000u);
        const __nv_bfloat16 rb = __float2bfloat16(r);
        *(u16*)(smem + OFF_W2L + j * STW2 + k * 2) = *(const u16*)&rb;
    }
    if (tid < 128) ((float*)(smem + OFF_B1S))[tid] = b1[tid];
    if (tid < 32)  ((float*)(smem + OFF_B2S))[tid] = b2[tid];
    if (tid < 64)  ((float*)(smem + OFF_W3S))[tid] = W3[tid];
    if (tid < 2)   ((float*)(smem + OFF_B3S))[tid] = b3[tid];

    const float* b1s = (const float*)(smem + OFF_B1S);
    const float* b2s = (const float*)(smem + OFF_B2S);
    const float* W3s = (const float*)(smem + OFF_W3S);
    const float* b3s = (const float*)(smem + OFF_B3S);
    float* h2s = (float*)(smem + OFF_H2 + g * 4352);   // [32][34] f32

    __syncthreads();   // weights staged (block-wide, once)

    #define GBAR96() asm volatile("bar.sync %0, %1;" :: "r"(bar96), "n"(96) : "memory")
    #define GBAR64() asm volatile("bar.sync %0, %1;" :: "r"(bar64), "n"(64) : "memory")

    const int tile0 = blockIdx.x * 4 + g;
    const int tstep = gridDim.x * 4;

    if (gt >= 64) {
        // ================= IO warp: gathers, packs (covered), bare STS bursts =====
        const int iolane = gt - 64;   // edge within tile
        const u32 wb = (u32)iolane * STA;

        int sN = 0, dN = 0;
        bool ve = false;
        uint4 p0h[16], p0l[16];       // packed chunk0: [0..7]=src cols 0..63, [8..15]=dst

        if (tile0 < ntiles) {
            const int eg = tile0 * TILE_E + iolane;
            ve = eg < E;
            sN = ve ? src[eg] : 0;
            dN = ve ? dst[eg] : 0;
            {   // stage src, pack, then dst, pack (bounds register peak)
                float4 raw[16];
                const float4* ps = (const float4*)(x + (size_t)sN * 64);
                #pragma unroll
                for (int i = 0; i < 16; ++i) raw[i] = ps[i];
                #pragma unroll
                for (int t8 = 0; t8 < 8; ++t8)
                    pack8(((const float*)raw) + 8 * t8, p0h[t8], p0l[t8]);
                const float4* pd = (const float4*)(x + (size_t)dN * 64);
                #pragma unroll
                for (int i = 0; i < 16; ++i) raw[i] = pd[i];
                #pragma unroll
                for (int t8 = 0; t8 < 8; ++t8)
                    pack8(((const float*)raw) + 8 * t8, p0h[8 + t8], p0l[8 + t8]);
            }
        }

        for (int tile = tile0; tile < ntiles; tile += tstep) {
            const int eg = tile * TILE_E + iolane;
            const size_t egc = ve ? (size_t)eg : 0;

            // ---- STS chunk0 from packed regs (pure stores; overlaps layer-3 prev) ----
            #pragma unroll
            for (int t8 = 0; t8 < 16; ++t8) {
                *(uint4*)(smem + aBase + wb + t8 * 16) = p0h[t8];
                *(uint4*)(smem + aBase + A_PART + wb + t8 * 16) = p0l[t8];
            }
            GBAR96();   // B1: c0 ready

            // ---- gather + pack chunk1 (covered by MMA chunk<8>) ----
            uint4 p1h[12], p1l[12];   // e: 8 chunks (cols 0..63), ns: 4 chunks (cols 64..95)
            {
                float4 e4[16];
                const float4* pe = (const float4*)(efeat + egc * 64);
                #pragma unroll
                for (int i = 0; i < 16; ++i) e4[i] = pe[i];
                float ns[32];
                #pragma unroll
                for (int j = 0; j < 10; ++j) {
                    ns[j]      = nodef[(size_t)sN * 10 + j];
                    ns[10 + j] = nodef[(size_t)dN * 10 + j];
                }
                ns[20] = edgef[egc * 2];
                ns[21] = edgef[egc * 2 + 1];
                #pragma unroll
                for (int j = 22; j < 32; ++j) ns[j] = 0.f;
                #pragma unroll
                for (int t8 = 0; t8 < 8; ++t8)
                    pack8(((const float*)e4) + 8 * t8, p1h[t8], p1l[t8]);
                #pragma unroll
                for (int t4 = 0; t4 < 4; ++t4)
                    pack8(ns + 8 * t4, p1h[8 + t4], p1l[8 + t4]);
            }
            GBAR96();   // B2: MMA done reading chunk0 cols

            // ---- STS chunk1 (pure stores) ----
            #pragma unroll
            for (int t8 = 0; t8 < 8; ++t8) {
                *(uint4*)(smem + aBase + wb + t8 * 16) = p1h[t8];
                *(uint4*)(smem + aBase + A_PART + wb + t8 * 16) = p1l[t8];
            }
            #pragma unroll
            for (int t4 = 0; t4 < 4; ++t4) {
                *(uint4*)(smem + aBase + wb + 128 + t4 * 16) = p1h[8 + t4];
                *(uint4*)(smem + aBase + A_PART + wb + 128 + t4 * 16) = p1l[8 + t4];
            }
            GBAR96();   // B3: c1 ready

            // ---- prefetch + pack next tile's chunk0 (covered by chunk<6>+epi+l2) ----
            {
                const int tn = tile + tstep;
                if (tn < ntiles) {
                    const int eg2 = tn * TILE_E + iolane;
                    ve = eg2 < E;
                    sN = ve ? src[eg2] : 0;
                    dN = ve ? dst[eg2] : 0;
                    float4 raw[16];
                    const float4* ps = (const float4*)(x + (size_t)sN * 64);
                    #pragma unroll
                    for (int i = 0; i < 16; ++i) raw[i] = ps[i];
                    #pragma unroll
                    for (int t8 = 0; t8 < 8; ++t8)
                        pack8(((const float*)raw) + 8 * t8, p0h[t8], p0l[t8]);
                    const float4* pd = (const float4*)(x + (size_t)dN * 64);
                    #pragma unroll
                    for (int i = 0; i < 16; ++i) raw[i] = pd[i];
                    #pragma unroll
                    for (int t8 = 0; t8 < 8; ++t8)
                        pack8(((const float*)raw) + 8 * t8, p0h[8 + t8], p0l[8 + t8]);
                }
            }
            GBAR96();   // B6: layer-2 reads done -> A free for next STS-c0
        }
    } else {
        // ================= MMA warps: pure compute =================
        const int nh = gt >> 5;   // n-half (0/1)

        const int aRow = ((lane >> 3) & 1) * 8 + (lane & 7);
        const u32 aOff = (u32)aRow * STA + (u32)(lane >> 4) * 16;
        const u32 aBH  = sb + aBase + aOff;
        const u32 aBL  = aBH + A_PART;
        const int bSel = lane >> 4, bKh = (lane >> 3) & 1, bRow = lane & 7;
        const u32 b1off = (u32)(nh * 64 + bSel * 8 + bRow) * STW1 + (u32)bKh * 16;
        const u32 b1H  = sb + OFF_W1H + b1off;
        const u32 b1L  = sb + OFF_W1L + b1off;
        const u32 b2off = (u32)(nh * 16 + bSel * 8 + bRow) * STW2 + (u32)bKh * 16;
        const u32 b2H  = sb + OFF_W2H + b2off;
        const u32 b2L  = sb + OFF_W2L + b2off;

        int prev_ebase = -1;

        for (int tile = tile0; tile < ntiles; tile += tstep) {
            const int ebase = tile * TILE_E;

            // ---- layer 3 of previous tile (overlaps IO's STS-c0) ----
            if (prev_ebase >= 0) {
                const int row = gt >> 1, cls = gt & 1;
                float sum = b3s[cls];
                #pragma unroll
                for (int k = 0; k < 32; ++k)
                    sum = fmaf(h2s[row * 34 + k], W3s[cls * 32 + k], sum);
                const int ego = prev_ebase + row;
                if (ego < E) out[(size_t)ego * 2 + cls] = sum;
            }
            GBAR96();   // B1: c0 ready

            float acc[2][8][4];
            #pragma unroll
            for (int i = 0; i < 2; ++i)
                #pragma unroll
                for (int j = 0; j < 8; ++j)
                    #pragma unroll
                    for (int p = 0; p < 4; ++p) acc[i][j][p] = 0.f;

            l1_chunk<8>(acc, aBH, aBL, b1H, b1L, 0);
            GBAR96();   // B2: chunk0 reads done (IO may STS c1)
            GBAR96();   // B3: c1 ready

            l1_chunk<6>(acc, aBH, aBL, b1H, b1L, 8 * 32);
            GBAR64();   // B4: both MMA warps done reading A

            // ---- epilogue 1: bias + relu + split -> h1 into A buffers ----
            #pragma unroll
            for (int mb = 0; mb < 2; ++mb) {
                const int r0 = mb * 16 + (lane >> 2);
                #pragma unroll
                for (int nbl = 0; nbl < 8; ++nbl) {
                    const int n0 = nh * 64 + nbl * 8 + 2 * (lane & 3);
                    const float bb0 = b1s[n0], bb1 = b1s[n0 + 1];
                    float f0 = fmaxf(acc[mb][nbl][0] + bb0, 0.f);
                    float f1 = fmaxf(acc[mb][nbl][1] + bb1, 0.f);
                    u32 hp, lp;
                    splitp(f0, f1, hp, lp);
                    *(u32*)(smem + aBase + r0 * STA + n0 * 2) = hp;
                    *(u32*)(smem + aBase + A_PART + r0 * STA + n0 * 2) = lp;
                    f0 = fmaxf(acc[mb][nbl][2] + bb0, 0.f);
                    f1 = fmaxf(acc[mb][nbl][3] + bb1, 0.f);
                    splitp(f0, f1, hp, lp);
                    *(u32*)(smem + aBase + (r0 + 8) * STA + n0 * 2) = hp;
                    *(u32*)(smem + aBase + A_PART + (r0 + 8) * STA + n0 * 2) = lp;
                }
            }
            GBAR64();   // B5: h1 ready

            // ---- layer 2: h1[32x128] @ W2^T -> h2[32x32]; warp owns 32r x 16c ----
            float acc2[2][2][4], acc2c[2][2][4];
            #pragma unroll
            for (int i = 0; i < 2; ++i)
                #pragma unroll
                for (int j = 0; j < 2; ++j)
                    #pragma unroll
                    for (int p = 0; p < 4; ++p) { acc2[i][j][p] = 0.f; acc2c[i][j][p] = 0.f; }

            #pragma unroll
            for (int ks = 0; ks < 8; ++ks) {
                u32 ah[2][4], al[2][4], bh[4], bl[4];
                #pragma unroll
                for (int mb = 0; mb < 2; ++mb) {
                    ldm4(aBH + mb * (16 * STA) + ks * 32, ah[mb]);
                    ldm4(aBL + mb * (16 * STA) + ks * 32, al[mb]);
                }
                ldm4(b2H + ks * 32, bh);
                ldm4(b2L + ks * 32, bl);
                #pragma unroll
                for (int mb = 0; mb < 2; ++mb) {
                    mma_bf16(acc2[mb][0],  ah[mb], bh[0], bh[1]);
                    mma_bf16(acc2[mb][1],  ah[mb], bh[2], bh[3]);
                }
                #pragma unroll
                for (int mb = 0; mb < 2; ++mb) {
                    mma_bf16(acc2c[mb][0], al[mb], bh[0], bh[1]);
                    mma_bf16(acc2c[mb][1], al[mb], bh[2], bh[3]);
                }
                #pragma unroll
                for (int mb = 0; mb < 2; ++mb) {
                    mma_bf16(acc2c[mb][0], ah[mb], bl[0], bl[1]);
                    mma_bf16(acc2c[mb][1], ah[mb], bl[2], bl[3]);
                }
            }

            // ---- epilogue 2: bias + relu -> h2s ----
            #pragma unroll
            for (int mb = 0; mb < 2; ++mb) {
                const int r0 = mb * 16 + (lane >> 2);
                #pragma unroll
                for (int nbl = 0; nbl < 2; ++nbl) {
                    const int c0 = nh * 16 + nbl * 8 + 2 * (lane & 3);
                    const float bb0 = b2s[c0], bb1 = b2s[c0 + 1];
                    *(float2*)(h2s + r0 * 34 + c0) =
                        make_float2(fmaxf(acc2[mb][nbl][0] + acc2c[mb][nbl][0] + bb0, 0.f),
                                    fmaxf(acc2[mb][nbl][1] + acc2c[mb][nbl][1] + bb1, 0.f));
                    *(float2*)(h2s + (r0 + 8) * 34 + c0) =
                        make_float2(fmaxf(acc2[mb][nbl][2] + acc2c[mb][nbl][2] + bb0, 0.f),
                                    fmaxf(acc2[mb][nbl][3] + acc2c[mb][nbl][3] + bb1, 0.f));
                }
            }
            GBAR96();   // B6: h2s ready; layer-2 A reads done (A free for IO)

            prev_ebase = ebase;
        }

        // ---- final layer 3 for the last tile ----
        if (prev_ebase >= 0) {
            const int row = gt >> 1, cls = gt & 1;
            float sum = b3s[cls];
            #pragma unroll
            for (int k = 0; k < 32; ++k)
                sum = fmaf(h2s[row * 34 + k], W3s[cls * 32 + k], sum);
            const int ego = prev_ebase + row;
            if (ego < E) out[(size_t)ego * 2 + cls] = sum;
        }
    }
    #undef GBAR96
    #undef GBAR64
}

extern "C" void kernel_launch(void* const* d_in, const int* in_sizes, int n_in,
                              void* d_out, int out_size) {
    const float* x     = (const float*)d_in[0];
    const float* efeat = (const float*)d_in[1];
    const float* nodef = (const float*)d_in[2];
    const float* edgef = (const float*)d_in[3];
    const int*   src   = (const int*)d_in[4];
    const int*   dst   = (const int*)d_in[5];
    const float* W1    = (const float*)d_in[6];
    const float* b1    = (const float*)d_in[7];
    const float* W2    = (const float*)d_in[8];
    const float* b2    = (const float*)d_in[9];
    const float* W3    = (const float*)d_in[10];
    const float* b3    = (const float*)d_in[11];
    float* out = (float*)d_out;

    const int E      = in_sizes[4];
    const int ntiles = (E + TILE_E - 1) / TILE_E;

    cudaFuncSetAttribute(edge_mlp_hmma, cudaFuncAttributeMaxDynamicSharedMemorySize, SMEM_SZ);
    int grid = 152;
    const int need = (ntiles + 3) / 4;
    if (grid > need) grid = need;
    edge_mlp_hmma<<<grid, NTHR, SMEM_SZ>>>(x, efeat, nodef, edgef, src, dst,
                                           W1, b1, W2, b2, W3, b3, out, E, ntiles);
}

// round 17
// speedup vs baseline: 1.3632x; 1.2754x over previous
#include <cuda_runtime.h>
#include <cuda_fp16.h>
#include <cstdint>

typedef uint32_t u32;
typedef unsigned short u16;

#define NTHR   384
#define TILE_E 32          // per group (4 groups x [2 MMA warps + 1 IO warp])
#define K1     214

#define STA  272           // A/h1 row stride bytes (136 fp16)
#define STW1 464           // W1 row stride (232 fp16)
#define STW2 272

#define A_PART   8704      // 32 rows * STA
#define OFF_B1S  0
#define OFF_B2S  512
#define OFF_W3S  640
#define OFF_B3S  896
#define OFF_A0   1024      // group g A: hi at OFF_A0+g*2*A_PART, lo at +A_PART
#define OFF_W1   (OFF_A0 + 8 * A_PART)          // 70656  (single fp16 image)
#define OFF_W2   (OFF_W1 + 128 * STW1)          // 130048
#define OFF_H2   (OFF_W2 + 32 * STW2)           // 138752; per group +4352
#define SMEM_SZ  (OFF_H2 + 4 * 32 * 34 * 4)     // 156160 B

__device__ __forceinline__ u32 s2u(const void* p) {
    u32 a;
    asm("{ .reg .u64 t; cvta.to.shared.u64 t, %1; cvt.u32.u64 %0, t; }" : "=r"(a) : "l"(p));
    return a;
}
__device__ __forceinline__ void ldm4(u32 addr, u32* r) {
    asm volatile("ldmatrix.sync.aligned.m8n8.x4.shared.b16 {%0,%1,%2,%3}, [%4];"
                 : "=r"(r[0]), "=r"(r[1]), "=r"(r[2]), "=r"(r[3]) : "r"(addr));
}
__device__ __forceinline__ void mma_f16(float* c, const u32* a, u32 b0, u32 b1) {
    asm volatile("mma.sync.aligned.m16n8k16.row.col.f32.f16.f16.f32 "
                 "{%0,%1,%2,%3}, {%4,%5,%6,%7}, {%8,%9}, {%0,%1,%2,%3};"
                 : "+f"(c[0]), "+f"(c[1]), "+f"(c[2]), "+f"(c[3])
                 : "r"(a[0]), "r"(a[1]), "r"(a[2]), "r"(a[3]), "r"(b0), "r"(b1));
}
__device__ __forceinline__ u32 cvt2h(float a, float b) {
    u32 r;
    asm("cvt.rn.f16x2.f32 %0, %2, %1;" : "=r"(r) : "f"(a), "f"(b));
    return r;
}
// split (a,b) into packed-fp16x2 hi + fp16x2 residual
__device__ __forceinline__ void splitp(float a, float b, u32& hp, u32& lp) {
    hp = cvt2h(a, b);
    const __half2 h2 = *reinterpret_cast<const __half2*>(&hp);
    const float fa = __low2float(h2);
    const float fb = __high2float(h2);
    lp = cvt2h(a - fa, b - fb);
}
// pack 8 floats into hi uint4 + lo uint4 (no store)
__device__ __forceinline__ void pack8(const float* v, uint4& hv, uint4& lv) {
    splitp(v[0], v[1], hv.x, lv.x);
    splitp(v[2], v[3], hv.y, lv.y);
    splitp(v[4], v[5], hv.z, lv.z);
    splitp(v[6], v[7], hv.w, lv.w);
}

// layer-1 chunk, term-outer ordering; warp tile 32 rows x 64 cols; 2-term fp16
template <int NKS>
__device__ __forceinline__ void l1_chunk(float (&acc)[2][8][4],
                                         u32 aBH, u32 aBL,
                                         u32 b1B, u32 bk)
{
    #pragma unroll
    for (int ks = 0; ks < NKS; ++ks) {
        u32 ah[2][4], al[2][4], bq[4][4];
        #pragma unroll
        for (int mb = 0; mb < 2; ++mb) {
            ldm4(aBH + mb * (16 * STA) + ks * 32, ah[mb]);
            ldm4(aBL + mb * (16 * STA) + ks * 32, al[mb]);
        }
        #pragma unroll
        for (int np = 0; np < 4; ++np)
            ldm4(b1B + np * (16 * STW1) + bk + ks * 32, bq[np]);
        // term 1: Ah*B (16 independent MMAs)
        #pragma unroll
        for (int np = 0; np < 4; ++np)
            #pragma unroll
            for (int mb = 0; mb < 2; ++mb) {
                mma_f16(acc[mb][2 * np],     ah[mb], bq[np][0], bq[np][1]);
                mma_f16(acc[mb][2 * np + 1], ah[mb], bq[np][2], bq[np][3]);
            }
        // term 2: Al*B
        #pragma unroll
        for (int np = 0; np < 4; ++np)
            #pragma unroll
            for (int mb = 0; mb < 2; ++mb) {
                mma_f16(acc[mb][2 * np],     al[mb], bq[np][0], bq[np][1]);
                mma_f16(acc[mb][2 * np + 1], al[mb], bq[np][2], bq[np][3]);
            }
    }
}

extern "C" __global__ void __launch_bounds__(NTHR, 1)
edge_mlp_hmma(const float* __restrict__ x, const float* __restrict__ efeat,
              const float* __restrict__ nodef, const float* __restrict__ edgef,
              const int* __restrict__ src, const int* __restrict__ dst,
              const float* __restrict__ W1, const float* __restrict__ b1,
              const float* __restrict__ W2, const float* __restrict__ b2,
              const float* __restrict__ W3, const float* __restrict__ b3,
              float* __restrict__ out, int E, int ntiles)
{
    extern __shared__ char smem[];
    const u32 sb   = s2u(smem);
    const int tid  = threadIdx.x;
    const int g    = tid / 96;          // pipeline group 0..3
    const int gt   = tid - g * 96;      // thread within group
    const int lane = tid & 31;
    const int bar96 = 1 + g;            // group-wide barrier (96 threads)
    const int bar64 = 5 + g;            // MMA-warps-only barrier (64 threads)

    const u32 aBase = OFF_A0 + (u32)g * (2 * A_PART);   // hi base; lo = +A_PART

    // ---------- one-time weight staging (whole block): single fp16 ----------
    for (int i = tid; i < 128 * 232; i += NTHR) {
        const int j = i / 232, k = i - j * 232;
        const float v = (k < K1) ? W1[j * K1 + k] : 0.f;
        const __half h = __float2half_rn(v);
        *(u16*)(smem + OFF_W1 + j * STW1 + k * 2) = *(const u16*)&h;
    }
    for (int i = tid; i < 32 * 136; i += NTHR) {
        const int j = i / 136, k = i - j * 136;
        const float v = (k < 128) ? W2[j * 128 + k] : 0.f;
        const __half h = __float2half_rn(v);
        *(u16*)(smem + OFF_W2 + j * STW2 + k * 2) = *(const u16*)&h;
    }
    if (tid < 128) ((float*)(smem + OFF_B1S))[tid] = b1[tid];
    if (tid < 32)  ((float*)(smem + OFF_B2S))[tid] = b2[tid];
    if (tid < 64)  ((float*)(smem + OFF_W3S))[tid] = W3[tid];
    if (tid < 2)   ((float*)(smem + OFF_B3S))[tid] = b3[tid];

    const float* b1s = (const float*)(smem + OFF_B1S);
    const float* b2s = (const float*)(smem + OFF_B2S);
    const float* W3s = (const float*)(smem + OFF_W3S);
    const float* b3s = (const float*)(smem + OFF_B3S);
    float* h2s = (float*)(smem + OFF_H2 + g * 4352);   // [32][34] f32

    __syncthreads();   // weights staged (block-wide, once)

    #define GBAR96() asm volatile("bar.sync %0, %1;" :: "r"(bar96), "n"(96) : "memory")
    #define GBAR64() asm volatile("bar.sync %0, %1;" :: "r"(bar64), "n"(64) : "memory")

    const int tile0 = blockIdx.x * 4 + g;
    const int tstep = gridDim.x * 4;

    if (gt >= 64) {
        // ================= IO warp: gathers, packs (covered), bare STS bursts =====
        const int iolane = gt - 64;   // edge within tile
        const u32 wb = (u32)iolane * STA;

        int sN = 0, dN = 0;
        bool ve = false;
        uint4 p0h[16], p0l[16];       // packed chunk0: [0..7]=src cols 0..63, [8..15]=dst

        if (tile0 < ntiles) {
            const int eg = tile0 * TILE_E + iolane;
            ve = eg < E;
            sN = ve ? src[eg] : 0;
            dN = ve ? dst[eg] : 0;
            {   // stage src, pack, then dst, pack (bounds register peak)
                float4 raw[16];
                const float4* ps = (const float4*)(x + (size_t)sN * 64);
                #pragma unroll
                for (int i = 0; i < 16; ++i) raw[i] = ps[i];
                #pragma unroll
                for (int t8 = 0; t8 < 8; ++t8)
                    pack8(((const float*)raw) + 8 * t8, p0h[t8], p0l[t8]);
                const float4* pd = (const float4*)(x + (size_t)dN * 64);
                #pragma unroll
                for (int i = 0; i < 16; ++i) raw[i] = pd[i];
                #pragma unroll
                for (int t8 = 0; t8 < 8; ++t8)
                    pack8(((const float*)raw) + 8 * t8, p0h[8 + t8], p0l[8 + t8]);
            }
        }

        for (int tile = tile0; tile < ntiles; tile += tstep) {
            const int eg = tile * TILE_E + iolane;
            const size_t egc = ve ? (size_t)eg : 0;

            // ---- STS chunk0 from packed regs (pure stores; overlaps layer-3 prev) ----
            #pragma unroll
            for (int t8 = 0; t8 < 16; ++t8) {
                *(uint4*)(smem + aBase + wb + t8 * 16) = p0h[t8];
                *(uint4*)(smem + aBase + A_PART + wb + t8 * 16) = p0l[t8];
            }
            GBAR96();   // B1: c0 ready

            // ---- gather + pack chunk1 (covered by MMA chunk<8>) ----
            uint4 p1h[12], p1l[12];   // e: 8 chunks (cols 0..63), ns: 4 chunks (cols 64..95)
            {
                float4 e4[16];
                const float4* pe = (const float4*)(efeat + egc * 64);
                #pragma unroll
                for (int i = 0; i < 16; ++i) e4[i] = pe[i];
                float ns[32];
                #pragma unroll
                for (int j = 0; j < 10; ++j) {
                    ns[j]      = nodef[(size_t)sN * 10 + j];
                    ns[10 + j] = nodef[(size_t)dN * 10 + j];
                }
                ns[20] = edgef[egc * 2];
                ns[21] = edgef[egc * 2 + 1];
                #pragma unroll
                for (int j = 22; j < 32; ++j) ns[j] = 0.f;
                #pragma unroll
                for (int t8 = 0; t8 < 8; ++t8)
                    pack8(((const float*)e4) + 8 * t8, p1h[t8], p1l[t8]);
                #pragma unroll
                for (int t4 = 0; t4 < 4; ++t4)
                    pack8(ns + 8 * t4, p1h[8 + t4], p1l[8 + t4]);
            }
            GBAR96();   // B2: MMA done reading chunk0 cols

            // ---- STS chunk1 (pure stores) ----
            #pragma unroll
            for (int t8 = 0; t8 < 8; ++t8) {
                *(uint4*)(smem + aBase + wb + t8 * 16) = p1h[t8];
                *(uint4*)(smem + aBase + A_PART + wb + t8 * 16) = p1l[t8];
            }
            #pragma unroll
            for (int t4 = 0; t4 < 4; ++t4) {
                *(uint4*)(smem + aBase + wb + 128 + t4 * 16) = p1h[8 + t4];
                *(uint4*)(smem + aBase + A_PART + wb + 128 + t4 * 16) = p1l[8 + t4];
            }
            GBAR96();   // B3: c1 ready

            // ---- prefetch + pack next tile's chunk0 (covered by chunk<6>+epi+l2) ----
            {
                const int tn = tile + tstep;
                if (tn < ntiles) {
                    const int eg2 = tn * TILE_E + iolane;
                    ve = eg2 < E;
                    sN = ve ? src[eg2] : 0;
                    dN = ve ? dst[eg2] : 0;
                    float4 raw[16];
                    const float4* ps = (const float4*)(x + (size_t)sN * 64);
                    #pragma unroll
                    for (int i = 0; i < 16; ++i) raw[i] = ps[i];
                    #pragma unroll
                    for (int t8 = 0; t8 < 8; ++t8)
                        pack8(((const float*)raw) + 8 * t8, p0h[t8], p0l[t8]);
                    const float4* pd = (const float4*)(x + (size_t)dN * 64);
                    #pragma unroll
                    for (int i = 0; i < 16; ++i) raw[i] = pd[i];
                    #pragma unroll
                    for (int t8 = 0; t8 < 8; ++t8)
                        pack8(((const float*)raw) + 8 * t8, p0h[8 + t8], p0l[8 + t8]);
                }
            }
            GBAR96();   // B6: layer-2 reads done -> A free for next STS-c0
        }
    } else {
        // ================= MMA warps: pure compute =================
        const int nh = gt >> 5;   // n-half (0/1)

        const int aRow = ((lane >> 3) & 1) * 8 + (lane & 7);
        const u32 aOff = (u32)aRow * STA + (u32)(lane >> 4) * 16;
        const u32 aBH  = sb + aBase + aOff;
        const u32 aBL  = aBH + A_PART;
        const int bSel = lane >> 4, bKh = (lane >> 3) & 1, bRow = lane & 7;
        const u32 b1off = (u32)(nh * 64 + bSel * 8 + bRow) * STW1 + (u32)bKh * 16;
        const u32 b1B  = sb + OFF_W1 + b1off;
        const u32 b2off = (u32)(nh * 16 + bSel * 8 + bRow) * STW2 + (u32)bKh * 16;
        const u32 b2B  = sb + OFF_W2 + b2off;

        int prev_ebase = -1;

        for (int tile = tile0; tile < ntiles; tile += tstep) {
            const int ebase = tile * TILE_E;

            // ---- layer 3 of previous tile (overlaps IO's STS-c0) ----
            if (prev_ebase >= 0) {
                const int row = gt >> 1, cls = gt & 1;
                float sum = b3s[cls];
                #pragma unroll
                for (int k = 0; k < 32; ++k)
                    sum = fmaf(h2s[row * 34 + k], W3s[cls * 32 + k], sum);
                const int ego = prev_ebase + row;
                if (ego < E) out[(size_t)ego * 2 + cls] = sum;
            }
            GBAR96();   // B1: c0 ready

            float acc[2][8][4];
            #pragma unroll
            for (int i = 0; i < 2; ++i)
                #pragma unroll
                for (int j = 0; j < 8; ++j)
                    #pragma unroll
                    for (int p = 0; p < 4; ++p) acc[i][j][p] = 0.f;

            l1_chunk<8>(acc, aBH, aBL, b1B, 0);
            GBAR96();   // B2: chunk0 reads done (IO may STS c1)
            GBAR96();   // B3: c1 ready

            l1_chunk<6>(acc, aBH, aBL, b1B, 8 * 32);
            GBAR64();   // B4: both MMA warps done reading A

            // ---- epilogue 1: bias + relu + split -> h1 into A buffers ----
            #pragma unroll
            for (int mb = 0; mb < 2; ++mb) {
                const int r0 = mb * 16 + (lane >> 2);
                #pragma unroll
                for (int nbl = 0; nbl < 8; ++nbl) {
                    const int n0 = nh * 64 + nbl * 8 + 2 * (lane & 3);
                    const float bb0 = b1s[n0], bb1 = b1s[n0 + 1];
                    float f0 = fmaxf(acc[mb][nbl][0] + bb0, 0.f);
                    float f1 = fmaxf(acc[mb][nbl][1] + bb1, 0.f);
                    u32 hp, lp;
                    splitp(f0, f1, hp, lp);
                    *(u32*)(smem + aBase + r0 * STA + n0 * 2) = hp;
                    *(u32*)(smem + aBase + A_PART + r0 * STA + n0 * 2) = lp;
                    f0 = fmaxf(acc[mb][nbl][2] + bb0, 0.f);
                    f1 = fmaxf(acc[mb][nbl][3] + bb1, 0.f);
                    splitp(f0, f1, hp, lp);
                    *(u32*)(smem + aBase + (r0 + 8) * STA + n0 * 2) = hp;
                    *(u32*)(smem + aBase + A_PART + (r0 + 8) * STA + n0 * 2) = lp;
                }
            }
            GBAR64();   // B5: h1 ready

            // ---- layer 2: h1[32x128] @ W2^T -> h2[32x32]; warp owns 32r x 16c ----
            float acc2[2][2][4], acc2c[2][2][4];
            #pragma unroll
            for (int i = 0; i < 2; ++i)
                #pragma unroll
                for (int j = 0; j < 2; ++j)
                    #pragma unroll
                    for (int p = 0; p < 4; ++p) { acc2[i][j][p] = 0.f; acc2c[i][j][p] = 0.f; }

            #pragma unroll
            for (int ks = 0; ks < 8; ++ks) {
                u32 ah[2][4], al[2][4], bq[4];
                #pragma unroll
                for (int mb = 0; mb < 2; ++mb) {
                    ldm4(aBH + mb * (16 * STA) + ks * 32, ah[mb]);
                    ldm4(aBL + mb * (16 * STA) + ks * 32, al[mb]);
                }
                ldm4(b2B + ks * 32, bq);
                #pragma unroll
                for (int mb = 0; mb < 2; ++mb) {
                    mma_f16(acc2[mb][0],  ah[mb], bq[0], bq[1]);
                    mma_f16(acc2[mb][1],  ah[mb], bq[2], bq[3]);
                }
                #pragma unroll
                for (int mb = 0; mb < 2; ++mb) {
                    mma_f16(acc2c[mb][0], al[mb], bq[0], bq[1]);
                    mma_f16(acc2c[mb][1], al[mb], bq[2], bq[3]);
                }
            }

            // ---- epilogue 2: bias + relu -> h2s ----
            #pragma unroll
            for (int mb = 0; mb < 2; ++mb) {
                const int r0 = mb * 16 + (lane >> 2);
                #pragma unroll
                for (int nbl = 0; nbl < 2; ++nbl) {
                    const int c0 = nh * 16 + nbl * 8 + 2 * (lane & 3);
                    const float bb0 = b2s[c0], bb1 = b2s[c0 + 1];
                    *(float2*)(h2s + r0 * 34 + c0) =
                        make_float2(fmaxf(acc2[mb][nbl][0] + acc2c[mb][nbl][0] + bb0, 0.f),
                                    fmaxf(acc2[mb][nbl][1] + acc2c[mb][nbl][1] + bb1, 0.f));
                    *(float2*)(h2s + (r0 + 8) * 34 + c0) =
                        make_float2(fmaxf(acc2[mb][nbl][2] + acc2c[mb][nbl][2] + bb0, 0.f),
                                    fmaxf(acc2[mb][nbl][3] + acc2c[mb][nbl][3] + bb1, 0.f));
                }
            }
            GBAR96();   // B6: h2s ready; layer-2 A reads done (A free for IO)

            prev_ebase = ebase;
        }

        // ---- final layer 3 for the last tile ----
        if (prev_ebase >= 0) {
            const int row = gt >> 1, cls = gt & 1;
            float sum = b3s[cls];
            #pragma unroll
            for (int k = 0; k < 32; ++k)
                sum = fmaf(h2s[row * 34 + k], W3s[cls * 32 + k], sum);
            const int ego = prev_ebase + row;
            if (ego < E) out[(size_t)ego * 2 + cls] = sum;
        }
    }
    #undef GBAR96
    #undef GBAR64
}

extern "C" void kernel_launch(void* const* d_in, const int* in_sizes, int n_in,
                              void* d_out, int out_size) {
    const float* x     = (const float*)d_in[0];
    const float* efeat = (const float*)d_in[1];
    const float* nodef = (const float*)d_in[2];
    const float* edgef = (const float*)d_in[3];
    const int*   src   = (const int*)d_in[4];
    const int*   dst   = (const int*)d_in[5];
    const float* W1    = (const float*)d_in[6];
    const float* b1    = (const float*)d_in[7];
    const float* W2    = (const float*)d_in[8];
    const float* b2    = (const float*)d_in[9];
    const float* W3    = (const float*)d_in[10];
    const float* b3    = (const float*)d_in[11];
    float* out = (float*)d_out;

    const int E      = in_sizes[4];
    const int ntiles = (E + TILE_E - 1) / TILE_E;

    cudaFuncSetAttribute(edge_mlp_hmma, cudaFuncAttributeMaxDynamicSharedMemorySize, SMEM_SZ);
    int grid = 152;
    const int need = (ntiles + 3) / 4;
    if (grid > need) grid = need;
    edge_mlp_hmma<<<grid, NTHR, SMEM_SZ>>>(x, efeat, nodef, edgef, src, dst,
                                           W1, b1, W2, b2, W3, b3, out, E, ntiles);
}